// round 6
// baseline (speedup 1.0000x reference)
#include <cuda_runtime.h>
#include <cuda_bf16.h>
#include <math.h>
#include <stdint.h>

typedef __nv_bfloat16 bf16;

// ---------------- problem dims (gpt-small) ----------------
#define LAYERS 8
#define HEADS  8
#define CDIM   256
#define VDIM   128
#define TDIM   1024
#define BDIM   32
#define FFDIM  1024
#define NTOK   (BDIM*TDIM)   // 32768

// ---------------- scratch (device globals) ----------------
__device__ __align__(128) float g_x  [(size_t)NTOK*CDIM];     // residual stream
__device__ __align__(128) bf16 g_hhi[(size_t)NTOK*CDIM], g_hlo[(size_t)NTOK*CDIM];
__device__ __align__(128) bf16 g_qvh[(size_t)NTOK*3*CDIM], g_qvl[(size_t)NTOK*3*CDIM];
__device__ __align__(128) bf16 g_yhi[(size_t)NTOK*CDIM], g_ylo[(size_t)NTOK*CDIM];
__device__ __align__(128) bf16 g_fhi[(size_t)NTOK*FFDIM], g_flo[(size_t)NTOK*FFDIM];
// transposed + split weights: [N,K] (K-major rows)
__device__ __align__(128) bf16 g_wqh[(size_t)LAYERS*3*CDIM*CDIM], g_wql[(size_t)LAYERS*3*CDIM*CDIM];
__device__ __align__(128) bf16 g_woh[(size_t)LAYERS*CDIM*CDIM],   g_wol[(size_t)LAYERS*CDIM*CDIM];
__device__ __align__(128) bf16 g_wfh[(size_t)LAYERS*FFDIM*CDIM],  g_wfl[(size_t)LAYERS*FFDIM*CDIM];
__device__ __align__(128) bf16 g_wph[(size_t)LAYERS*CDIM*FFDIM],  g_wpl[(size_t)LAYERS*CDIM*FFDIM];
__device__ __align__(128) bf16 g_wlh[(size_t)VDIM*CDIM],          g_wll[(size_t)VDIM*CDIM];

// ---------------- PTX helpers (sm_80-era only) ----------------
__device__ __forceinline__ uint32_t smem_u32(const void* p) {
    uint32_t a;
    asm("{ .reg .u64 t; cvta.to.shared.u64 t, %1; cvt.u32.u64 %0, t; }" : "=r"(a) : "l"(p));
    return a;
}
__device__ __forceinline__ void cp16(uint32_t dst, const void* src) {
    asm volatile("cp.async.cg.shared.global [%0], [%1], 16;" :: "r"(dst), "l"(src));
}
#define CP_COMMIT() asm volatile("cp.async.commit_group;" ::: "memory")
#define CP_WAIT(n)  asm volatile("cp.async.wait_group %0;" :: "n"(n) : "memory")

__device__ __forceinline__ void ldmx4(uint32_t* r, uint32_t addr) {
    asm volatile("ldmatrix.sync.aligned.m8n8.x4.shared.b16 {%0,%1,%2,%3}, [%4];"
        : "=r"(r[0]), "=r"(r[1]), "=r"(r[2]), "=r"(r[3]) : "r"(addr));
}
__device__ __forceinline__ void ldmx4t(uint32_t* r, uint32_t addr) {
    asm volatile("ldmatrix.sync.aligned.m8n8.x4.trans.shared.b16 {%0,%1,%2,%3}, [%4];"
        : "=r"(r[0]), "=r"(r[1]), "=r"(r[2]), "=r"(r[3]) : "r"(addr));
}
__device__ __forceinline__ void mma16816(float* c, const uint32_t* a, const uint32_t* b) {
    asm volatile("mma.sync.aligned.m16n8k16.row.col.f32.bf16.bf16.f32 "
        "{%0,%1,%2,%3}, {%4,%5,%6,%7}, {%8,%9}, {%0,%1,%2,%3};"
        : "+f"(c[0]), "+f"(c[1]), "+f"(c[2]), "+f"(c[3])
        : "r"(a[0]), "r"(a[1]), "r"(a[2]), "r"(a[3]), "r"(b[0]), "r"(b[1]));
}

// ---------------- misc math ----------------
__device__ __forceinline__ float gelu_f(float x) {
    float a = 0.7978845608028654f * (x + 0.044715f * x * x * x);
    a = fminf(fmaxf(a, -15.f), 15.f);
    float e = __expf(2.0f * a);
    float t = (e - 1.0f) / (e + 1.0f);
    return 0.5f * x * (1.0f + t);
}
__device__ __forceinline__ void bf_split(float v, bf16& hi, bf16& lo) {
    hi = __float2bfloat16(v);
    lo = __float2bfloat16(v - __bfloat162float(hi));
}
__device__ __forceinline__ uint32_t pack_hi2(float a, float b) {
    __nv_bfloat162 t; t.x = __float2bfloat16(a); t.y = __float2bfloat16(b);
    return *reinterpret_cast<uint32_t*>(&t);
}
__device__ __forceinline__ uint32_t pack_lo2(float a, float b) {
    bf16 ha = __float2bfloat16(a), hb = __float2bfloat16(b);
    __nv_bfloat162 t;
    t.x = __float2bfloat16(a - __bfloat162float(ha));
    t.y = __float2bfloat16(b - __bfloat162float(hb));
    return *reinterpret_cast<uint32_t*>(&t);
}

// ---------------- embed ----------------
__global__ void embed_kernel(const int* __restrict__ idx,
                             const float* __restrict__ tok,
                             const float* __restrict__ pos,
                             float* __restrict__ x)
{
    int i = blockIdx.x * blockDim.x + threadIdx.x;
    if (i >= NTOK * CDIM) return;
    int c = i & (CDIM - 1);
    int row = i >> 8;
    int t = row & (TDIM - 1);
    x[i] = tok[idx[row] * CDIM + c] + pos[t * CDIM + c];
}

// ---------------- layernorm -> split bf16 ----------------
__global__ void ln_kernel(const float* __restrict__ x,
                          const float* __restrict__ g,
                          const float* __restrict__ b,
                          bf16* __restrict__ ohi, bf16* __restrict__ olo)
{
    int row = blockIdx.x;
    int c = threadIdx.x;
    float v = x[(size_t)row * CDIM + c];
    float s = v, s2 = v * v;
    #pragma unroll
    for (int o = 16; o; o >>= 1) {
        s  += __shfl_xor_sync(0xffffffffu, s,  o);
        s2 += __shfl_xor_sync(0xffffffffu, s2, o);
    }
    __shared__ float ss[8], ss2[8], m_sh, r_sh;
    int w = c >> 5, lane = c & 31;
    if (lane == 0) { ss[w] = s; ss2[w] = s2; }
    __syncthreads();
    if (c == 0) {
        float S = 0.f, S2 = 0.f;
        #pragma unroll
        for (int i = 0; i < 8; i++) { S += ss[i]; S2 += ss2[i]; }
        float m = S * (1.0f / CDIM);
        float var = S2 * (1.0f / CDIM) - m * m;
        m_sh = m; r_sh = rsqrtf(var + 1e-5f);
    }
    __syncthreads();
    float o = (v - m_sh) * r_sh * g[c] + b[c];
    size_t i = (size_t)row * CDIM + c;
    bf16 hi, lo; bf_split(o, hi, lo);
    ohi[i] = hi; olo[i] = lo;
}

// ---------------- weight transpose + split: W[K,N] -> T[N,K] hi/lo ----------------
__global__ void wsplit_kernel(const float* __restrict__ W,
                              bf16* __restrict__ Thi, bf16* __restrict__ Tlo,
                              int K, int N)
{
    __shared__ float t[32][33];
    int n0 = blockIdx.x << 5, k0 = blockIdx.y << 5;
    int tx = threadIdx.x, ty = threadIdx.y;  // (32,8)
    #pragma unroll
    for (int j = 0; j < 4; j++)
        t[ty + j * 8][tx] = W[(size_t)(k0 + ty + j * 8) * N + n0 + tx];
    __syncthreads();
    #pragma unroll
    for (int j = 0; j < 4; j++) {
        int nl = ty + j * 8;
        float v = t[tx][nl];
        size_t o = (size_t)(n0 + nl) * K + k0 + tx;
        bf16 hi, lo; bf_split(v, hi, lo);
        Thi[o] = hi; Tlo[o] = lo;
    }
}

// ---------------- HMMA split-bf16 GEMM (same as round 4) ----------------
#define GST   10240
#define STAGE (4*GST)
#define GSMEM (2*STAGE)

__device__ __forceinline__ void g_fill(uint32_t st,
    const bf16* __restrict__ Ahi, const bf16* __restrict__ Alo,
    const bf16* __restrict__ Bhi, const bf16* __restrict__ Blo,
    int row0, int col0, int k0, int K, int tid)
{
    const bf16* base0 = Ahi + (size_t)row0 * K + k0;
    const bf16* base1 = Alo + (size_t)row0 * K + k0;
    const bf16* base2 = Bhi + (size_t)col0 * K + k0;
    const bf16* base3 = Blo + (size_t)col0 * K + k0;
    #pragma unroll
    for (int it = 0; it < 8; it++) {
        int i = tid + (it << 8);
        int mat = i >> 9, j = i & 511;
        int r = j >> 2, ch = j & 3;
        const bf16* src = (mat == 0) ? base0 : (mat == 1) ? base1 : (mat == 2) ? base2 : base3;
        cp16(st + mat * GST + r * 80 + ch * 16, src + (size_t)r * K + ch * 8);
    }
    CP_COMMIT();
}

template<bool GELU_, bool RES_, bool BF16OUT_, bool FP32OUT_>
__global__ void __launch_bounds__(256, 1) gemm_tc(
    const bf16* __restrict__ Ahi, const bf16* __restrict__ Alo,
    const bf16* __restrict__ Bhi, const bf16* __restrict__ Blo,
    const float* __restrict__ bias, const float* __restrict__ res,
    float* __restrict__ Cf, bf16* __restrict__ Chi, bf16* __restrict__ Clo,
    int M, int N, int K)
{
    extern __shared__ char smem[];
    const int tid  = threadIdx.x;
    const int wid  = tid >> 5;
    const int lane = tid & 31;
    const int warpM = wid & 3;
    const int warpN = wid >> 2;
    const int row0 = blockIdx.y << 7;
    const int col0 = blockIdx.x << 7;
    uint32_t sb = smem_u32(smem);

    float acc[2][8][4];
    #pragma unroll
    for (int mt = 0; mt < 2; mt++)
        #pragma unroll
        for (int nt = 0; nt < 8; nt++)
            #pragma unroll
            for (int j = 0; j < 4; j++) acc[mt][nt][j] = 0.f;

    const int nk = K >> 5;
    g_fill(sb, Ahi, Alo, Bhi, Blo, row0, col0, 0, K, tid);

    const uint32_t aoff_base = (uint32_t)((warpM * 32 + (lane & 15)) * 80 + ((lane >> 4) & 1) * 16);
    const uint32_t boff_base = (uint32_t)((warpN * 64 + ((lane >> 4) & 1) * 8 + (lane & 7)) * 80
                                          + ((lane >> 3) & 1) * 16);

    for (int kt = 0; kt < nk; kt++) {
        uint32_t st = sb + (uint32_t)(kt & 1) * STAGE;
        if (kt + 1 < nk) {
            g_fill(sb + (uint32_t)((kt + 1) & 1) * STAGE, Ahi, Alo, Bhi, Blo,
                   row0, col0, (kt + 1) << 5, K, tid);
            CP_WAIT(1);
        } else {
            CP_WAIT(0);
        }
        __syncthreads();

        #pragma unroll
        for (int k16 = 0; k16 < 2; k16++) {
            uint32_t ka = st + aoff_base + k16 * 32;
            uint32_t kb = st + boff_base + k16 * 32;
            uint32_t ah[2][4], al[2][4], bh[4][4], bl[4][4];
            ldmx4(ah[0], ka);
            ldmx4(ah[1], ka + 16 * 80);
            ldmx4(al[0], ka + GST);
            ldmx4(al[1], ka + GST + 16 * 80);
            #pragma unroll
            for (int nt2 = 0; nt2 < 4; nt2++) {
                ldmx4(bh[nt2], kb + 2 * GST + nt2 * (16 * 80));
                ldmx4(bl[nt2], kb + 3 * GST + nt2 * (16 * 80));
            }
            #pragma unroll
            for (int mt = 0; mt < 2; mt++)
                #pragma unroll
                for (int nt = 0; nt < 8; nt++) {
                    const uint32_t* bhp = &bh[nt >> 1][(nt & 1) * 2];
                    const uint32_t* blp = &bl[nt >> 1][(nt & 1) * 2];
                    mma16816(acc[mt][nt], ah[mt], bhp);
                    mma16816(acc[mt][nt], ah[mt], blp);
                    mma16816(acc[mt][nt], al[mt], bhp);
                }
        }
        __syncthreads();
    }

    const int g  = lane >> 2;
    const int tg = lane & 3;
    #pragma unroll
    for (int mt = 0; mt < 2; mt++) {
        #pragma unroll
        for (int half = 0; half < 2; half++) {
            int m = row0 + warpM * 32 + mt * 16 + g + half * 8;
            #pragma unroll
            for (int nt = 0; nt < 8; nt++) {
                int col = col0 + warpN * 64 + nt * 8 + tg * 2;
                float v0 = acc[mt][nt][half * 2 + 0];
                float v1 = acc[mt][nt][half * 2 + 1];
                if (bias) { v0 += bias[col]; v1 += bias[col + 1]; }
                if (GELU_) { v0 = gelu_f(v0); v1 = gelu_f(v1); }
                size_t o = (size_t)m * N + col;
                if (RES_) {
                    float2 r2 = *reinterpret_cast<const float2*>(&res[o]);
                    v0 += r2.x; v1 += r2.y;
                }
                if (FP32OUT_) {
                    *reinterpret_cast<float2*>(&Cf[o]) = make_float2(v0, v1);
                }
                if (BF16OUT_) {
                    bf16 h0, l0, h1, l1;
                    bf_split(v0, h0, l0); bf_split(v1, h1, l1);
                    __nv_bfloat162 hh; hh.x = h0; hh.y = h1;
                    __nv_bfloat162 ll; ll.x = l0; ll.y = l1;
                    *reinterpret_cast<__nv_bfloat162*>(&Chi[o]) = hh;
                    *reinterpret_cast<__nv_bfloat162*>(&Clo[o]) = ll;
                }
            }
        }
    }
}

// ================= HMMA flash attention =================
// smem layout (bytes):
#define AQ_HI 0
#define AQ_LO 5120
#define ASTG  10240
#define ASTGSZ 20480        // per stage: Khi|Klo|Vhi|Vlo each 5120
#define ARMAX 51200         // float[2][64]
#define ARSUM 51712         // float[2][64]
#define ALINV 52224         // float[64]
#define ASMEM 52480
#define ASCALE 0.17677669529663687f

__device__ __forceinline__ void a_fill_kv(uint32_t dst, const bf16* __restrict__ qh,
                                          const bf16* __restrict__ ql,
                                          size_t tokbase, int hcol, int k0, int tid)
{
    int r = tid >> 2, ch = tid & 3;
    size_t rowoff = tokbase + (size_t)(k0 + r) * 768;
    uint32_t so = (uint32_t)(r * 80 + ch * 16);
    cp16(dst + so,         qh + rowoff + 256 + hcol + ch * 8);
    cp16(dst + 5120 + so,  ql + rowoff + 256 + hcol + ch * 8);
    cp16(dst + 10240 + so, qh + rowoff + 512 + hcol + ch * 8);
    cp16(dst + 15360 + so, ql + rowoff + 512 + hcol + ch * 8);
}

__global__ void __launch_bounds__(256, 1) attn_tc(
    const bf16* __restrict__ qh, const bf16* __restrict__ ql,
    bf16* __restrict__ yhi, bf16* __restrict__ ylo)
{
    extern __shared__ char smem[];
    uint32_t sb = smem_u32(smem);
    const int tid = threadIdx.x, wid = tid >> 5, lane = tid & 31;
    const int warpM = wid & 3, warpN = wid >> 2;
    const int g = lane >> 2, tg = lane & 3;
    const int qt = (int)gridDim.x - 1 - (int)blockIdx.x;   // heavy tiles first
    const int bh = blockIdx.y;
    const int b = bh >> 3, h = bh & 7;
    const int q0 = qt * 64, hcol = h * 32;
    const size_t tokbase = (size_t)b * TDIM * 768;

    // load Q tile (hi/lo) + KV tile 0
    {
        int r = tid >> 2, ch = tid & 3;
        size_t qoff = tokbase + (size_t)(q0 + r) * 768 + hcol + ch * 8;
        uint32_t so = (uint32_t)(r * 80 + ch * 16);
        cp16(sb + AQ_HI + so, qh + qoff);
        cp16(sb + AQ_LO + so, ql + qoff);
    }
    a_fill_kv(sb + ASTG, qh, ql, tokbase, hcol, 0, tid);
    CP_COMMIT();

    const int r0 = warpM * 16 + g, r1 = r0 + 8;
    float m0 = -1e30f, m1 = -1e30f, l0 = 0.f, l1 = 0.f;
    float oc[4][4];
    #pragma unroll
    for (int n = 0; n < 4; n++)
        #pragma unroll
        for (int j = 0; j < 4; j++) oc[n][j] = 0.f;

    const uint32_t qa = sb + AQ_HI + (uint32_t)((warpM * 16 + (lane & 15)) * 80 + ((lane >> 4) & 1) * 16);
    const uint32_t kboff = (uint32_t)((warpN * 32 + ((lane >> 4) & 1) * 8 + (lane & 7)) * 80
                                      + ((lane >> 3) & 1) * 16);
    const uint32_t vaoff = (uint32_t)((warpN * 32 + (lane & 15)) * 80 + ((lane >> 4) & 1) * 16);

    float* rmax = (float*)(smem + ARMAX);
    float* rsum = (float*)(smem + ARSUM);
    float* linv = (float*)(smem + ALINV);

    for (int kt = 0; kt <= qt; kt++) {
        CP_WAIT(0);
        __syncthreads();
        uint32_t stg = sb + ASTG + (uint32_t)(kt & 1) * ASTGSZ;

        // ---- S = Q K^T (split 3-product, fp32 accum) ----
        float sc[4][4];
        #pragma unroll
        for (int n = 0; n < 4; n++)
            #pragma unroll
            for (int j = 0; j < 4; j++) sc[n][j] = 0.f;

        #pragma unroll
        for (int k16 = 0; k16 < 2; k16++) {
            uint32_t ah[4], al[4], bhh[2][4], bll[2][4];
            ldmx4(ah, qa + k16 * 32);
            ldmx4(al, qa + 5120 + k16 * 32);
            ldmx4(bhh[0], stg + kboff + k16 * 32);
            ldmx4(bhh[1], stg + kboff + k16 * 32 + 16 * 80);
            ldmx4(bll[0], stg + 5120 + kboff + k16 * 32);
            ldmx4(bll[1], stg + 5120 + kboff + k16 * 32 + 16 * 80);
            #pragma unroll
            for (int n = 0; n < 4; n++) {
                const uint32_t* bp = &bhh[n >> 1][(n & 1) * 2];
                const uint32_t* lp = &bll[n >> 1][(n & 1) * 2];
                mma16816(sc[n], ah, bp);
                mma16816(sc[n], ah, lp);
                mma16816(sc[n], al, bp);
            }
        }

        // ---- scale + causal mask ----
        const bool diag = (kt == qt);
        #pragma unroll
        for (int n = 0; n < 4; n++)
            #pragma unroll
            for (int j = 0; j < 4; j++) {
                float s = sc[n][j] * ASCALE;
                if (diag) {
                    int kc = warpN * 32 + n * 8 + tg * 2 + (j & 1);
                    int qr = (j < 2) ? r0 : r1;
                    if (kc > qr) s = -1e30f;
                }
                sc[n][j] = s;
            }

        // ---- row max (intra-warp, then cross warpN) ----
        float mx0 = -1e30f, mx1 = -1e30f;
        #pragma unroll
        for (int n = 0; n < 4; n++) {
            mx0 = fmaxf(mx0, fmaxf(sc[n][0], sc[n][1]));
            mx1 = fmaxf(mx1, fmaxf(sc[n][2], sc[n][3]));
        }
        mx0 = fmaxf(mx0, __shfl_xor_sync(0xffffffffu, mx0, 1));
        mx0 = fmaxf(mx0, __shfl_xor_sync(0xffffffffu, mx0, 2));
        mx1 = fmaxf(mx1, __shfl_xor_sync(0xffffffffu, mx1, 1));
        mx1 = fmaxf(mx1, __shfl_xor_sync(0xffffffffu, mx1, 2));
        if (tg == 0) { rmax[warpN * 64 + r0] = mx0; rmax[warpN * 64 + r1] = mx1; }
        __syncthreads();

        // prefetch next KV tile (overlaps softmax + PV)
        if (kt < qt) {
            a_fill_kv(sb + ASTG + (uint32_t)((kt + 1) & 1) * ASTGSZ,
                      qh, ql, tokbase, hcol, (kt + 1) * 64, tid);
            CP_COMMIT();
        }

        float M0 = fmaxf(rmax[r0], rmax[64 + r0]);
        float M1 = fmaxf(rmax[r1], rmax[64 + r1]);
        float n0 = fmaxf(m0, M0), n1 = fmaxf(m1, M1);
        float al0 = __expf(m0 - n0), al1 = __expf(m1 - n1);

        float s0 = 0.f, s1 = 0.f;
        #pragma unroll
        for (int n = 0; n < 4; n++) {
            #pragma unroll
            for (int j = 0; j < 4; j++) {
                float mn = (j < 2) ? n0 : n1;
                float p = __expf(sc[n][j] - mn);
                sc[n][j] = p;
                if (j < 2) s0 += p; else s1 += p;
            }
        }
        s0 += __shfl_xor_sync(0xffffffffu, s0, 1);
        s0 += __shfl_xor_sync(0xffffffffu, s0, 2);
        s1 += __shfl_xor_sync(0xffffffffu, s1, 1);
        s1 += __shfl_xor_sync(0xffffffffu, s1, 2);
        if (tg == 0) { rsum[warpN * 64 + r0] = s0; rsum[warpN * 64 + r1] = s1; }

        // build P fragments (registers only: C-frag -> A-frag identity)
        uint32_t ph[2][4], pl[2][4];
        #pragma unroll
        for (int t = 0; t < 2; t++) {
            ph[t][0] = pack_hi2(sc[2*t][0],   sc[2*t][1]);
            ph[t][1] = pack_hi2(sc[2*t][2],   sc[2*t][3]);
            ph[t][2] = pack_hi2(sc[2*t+1][0], sc[2*t+1][1]);
            ph[t][3] = pack_hi2(sc[2*t+1][2], sc[2*t+1][3]);
            pl[t][0] = pack_lo2(sc[2*t][0],   sc[2*t][1]);
            pl[t][1] = pack_lo2(sc[2*t][2],   sc[2*t][3]);
            pl[t][2] = pack_lo2(sc[2*t+1][0], sc[2*t+1][1]);
            pl[t][3] = pack_lo2(sc[2*t+1][2], sc[2*t+1][3]);
        }
        __syncthreads();
        float S0 = rsum[r0] + rsum[64 + r0];
        float S1 = rsum[r1] + rsum[64 + r1];
        l0 = l0 * al0 + S0; l1 = l1 * al1 + S1;
        m0 = n0; m1 = n1;
        #pragma unroll
        for (int n = 0; n < 4; n++) {
            oc[n][0] *= al0; oc[n][1] *= al0;
            oc[n][2] *= al1; oc[n][3] *= al1;
        }

        // ---- O += P V (V via ldmatrix.trans, split 3-product) ----
        #pragma unroll
        for (int t = 0; t < 2; t++) {
            uint32_t va = stg + 10240 + vaoff + (uint32_t)t * (16 * 80);
            uint32_t vh0[4], vh1[4], vl0[4], vl1[4];
            ldmx4t(vh0, va);
            ldmx4t(vh1, va + 32);
            ldmx4t(vl0, va + 5120);
            ldmx4t(vl1, va + 5120 + 32);
            #pragma unroll
            for (int n = 0; n < 4; n++) {
                const uint32_t* bp = (n < 2) ? &vh0[(n & 1) * 2] : &vh1[(n & 1) * 2];
                const uint32_t* lp = (n < 2) ? &vl0[(n & 1) * 2] : &vl1[(n & 1) * 2];
                mma16816(oc[n], ph[t], bp);
                mma16816(oc[n], pl[t], bp);
                mma16816(oc[n], ph[t], lp);
            }
        }
    }

    // ---- combine warpN halves + store ----
    __syncthreads();
    float* osum = (float*)(smem + ASTG);   // reuse KV region: 64 x 33 fp32
    if (warpN == 0) {
        #pragma unroll
        for (int n = 0; n < 4; n++)
            #pragma unroll
            for (int j = 0; j < 4; j++) {
                int rr = (j < 2) ? r0 : r1;
                int cc = n * 8 + tg * 2 + (j & 1);
                osum[rr * 33 + cc] = oc[n][j];
            }
    }
    if (warpN == 0 && tg == 0) { linv[r0] = 1.f / l0; linv[r1] = 1.f / l1; }
    __syncthreads();
    if (warpN == 1) {
        #pragma unroll
        for (int n = 0; n < 4; n++)
            #pragma unroll
            for (int j = 0; j < 4; j++) {
                int rr = (j < 2) ? r0 : r1;
                int cc = n * 8 + tg * 2 + (j & 1);
                osum[rr * 33 + cc] += oc[n][j];
            }
    }
    __syncthreads();
    {
        int row = tid >> 2, cg = tid & 3;
        float il = linv[row];
        size_t gout = (size_t)(b * TDIM + q0 + row) * CDIM + hcol + cg * 8;
        #pragma unroll
        for (int jp = 0; jp < 4; jp++) {
            float v0 = osum[row * 33 + cg * 8 + jp * 2]     * il;
            float v1 = osum[row * 33 + cg * 8 + jp * 2 + 1] * il;
            bf16 h0, lo0, h1, lo1;
            bf_split(v0, h0, lo0); bf_split(v1, h1, lo1);
            __nv_bfloat162 hh; hh.x = h0; hh.y = h1;
            __nv_bfloat162 ll; ll.x = lo0; ll.y = lo1;
            *reinterpret_cast<__nv_bfloat162*>(&yhi[gout + jp * 2]) = hh;
            *reinterpret_cast<__nv_bfloat162*>(&ylo[gout + jp * 2]) = ll;
        }
    }
}

// ---------------- host orchestration ----------------
extern "C" void kernel_launch(void* const* d_in, const int* in_sizes, int n_in,
                              void* d_out, int out_size)
{
    const int*   idx     = (const int*)  d_in[0];
    const float* tok_emb = (const float*)d_in[1];
    const float* pos_emb = (const float*)d_in[2];
    const float* ln1_g   = (const float*)d_in[3];
    const float* ln1_b   = (const float*)d_in[4];
    const float* wqkv    = (const float*)d_in[5];
    const float* bqkv    = (const float*)d_in[6];
    const float* wo      = (const float*)d_in[7];
    const float* bo      = (const float*)d_in[8];
    const float* ln2_g   = (const float*)d_in[9];
    const float* ln2_b   = (const float*)d_in[10];
    const float* wfc     = (const float*)d_in[11];
    const float* bfc     = (const float*)d_in[12];
    const float* wpr     = (const float*)d_in[13];
    const float* bpr     = (const float*)d_in[14];
    const float* lnf_g   = (const float*)d_in[15];
    const float* lnf_b   = (const float*)d_in[16];
    const float* w_lm    = (const float*)d_in[17];
    float* out = (float*)d_out;

    float *xp;
    bf16 *hhi, *hlo, *qvh, *qvl, *yhi, *ylo, *fhi, *flo;
    bf16 *wqh, *wql, *woh, *wol, *wfh, *wfl, *wph, *wpl, *wlh, *wll;
    cudaGetSymbolAddress((void**)&xp,   g_x);
    cudaGetSymbolAddress((void**)&hhi,  g_hhi);  cudaGetSymbolAddress((void**)&hlo, g_hlo);
    cudaGetSymbolAddress((void**)&qvh,  g_qvh);  cudaGetSymbolAddress((void**)&qvl, g_qvl);
    cudaGetSymbolAddress((void**)&yhi,  g_yhi);  cudaGetSymbolAddress((void**)&ylo, g_ylo);
    cudaGetSymbolAddress((void**)&fhi,  g_fhi);  cudaGetSymbolAddress((void**)&flo, g_flo);
    cudaGetSymbolAddress((void**)&wqh,  g_wqh);  cudaGetSymbolAddress((void**)&wql, g_wql);
    cudaGetSymbolAddress((void**)&woh,  g_woh);  cudaGetSymbolAddress((void**)&wol, g_wol);
    cudaGetSymbolAddress((void**)&wfh,  g_wfh);  cudaGetSymbolAddress((void**)&wfl, g_wfl);
    cudaGetSymbolAddress((void**)&wph,  g_wph);  cudaGetSymbolAddress((void**)&wpl, g_wpl);
    cudaGetSymbolAddress((void**)&wlh,  g_wlh);  cudaGetSymbolAddress((void**)&wll, g_wll);

    cudaFuncSetAttribute(gemm_tc<false, false, false, true>,
                         cudaFuncAttributeMaxDynamicSharedMemorySize, GSMEM);
    cudaFuncSetAttribute(gemm_tc<false, true, false, true>,
                         cudaFuncAttributeMaxDynamicSharedMemorySize, GSMEM);
    cudaFuncSetAttribute(gemm_tc<true, false, true, false>,
                         cudaFuncAttributeMaxDynamicSharedMemorySize, GSMEM);
    cudaFuncSetAttribute(gemm_tc<false, false, true, false>,
                         cudaFuncAttributeMaxDynamicSharedMemorySize, GSMEM);
    cudaFuncSetAttribute(attn_tc,
                         cudaFuncAttributeMaxDynamicSharedMemorySize, ASMEM);

    // ---- weight prep (transpose + bf16 split) ----
    dim3 wb(32, 8);
    for (int l = 0; l < LAYERS; l++) {
        wsplit_kernel<<<dim3(24, 8), wb>>>(wqkv + (size_t)l * CDIM * 3 * CDIM,
                                           wqh + (size_t)l * 3 * CDIM * CDIM,
                                           wql + (size_t)l * 3 * CDIM * CDIM, CDIM, 3 * CDIM);
        wsplit_kernel<<<dim3(8, 8),  wb>>>(wo + (size_t)l * CDIM * CDIM,
                                           woh + (size_t)l * CDIM * CDIM,
                                           wol + (size_t)l * CDIM * CDIM, CDIM, CDIM);
        wsplit_kernel<<<dim3(32, 8), wb>>>(wfc + (size_t)l * CDIM * FFDIM,
                                           wfh + (size_t)l * FFDIM * CDIM,
                                           wfl + (size_t)l * FFDIM * CDIM, CDIM, FFDIM);
        wsplit_kernel<<<dim3(8, 32), wb>>>(wpr + (size_t)l * FFDIM * CDIM,
                                           wph + (size_t)l * CDIM * FFDIM,
                                           wpl + (size_t)l * CDIM * FFDIM, FFDIM, CDIM);
    }
    wsplit_kernel<<<dim3(4, 8), wb>>>(w_lm, wlh, wll, CDIM, VDIM);

    embed_kernel<<<(NTOK * CDIM + 255) / 256, 256>>>(idx, tok_emb, pos_emb, xp);

    for (int l = 0; l < LAYERS; l++) {
        const float* bq  = bqkv + (size_t)l * 3 * CDIM;
        const float* bo_ = bo   + (size_t)l * CDIM;
        const float* bf  = bfc  + (size_t)l * FFDIM;
        const float* bp  = bpr  + (size_t)l * CDIM;
        bf16* Wqh = wqh + (size_t)l * 3 * CDIM * CDIM;  bf16* Wql = wql + (size_t)l * 3 * CDIM * CDIM;
        bf16* Woh = woh + (size_t)l * CDIM * CDIM;      bf16* Wol = wol + (size_t)l * CDIM * CDIM;
        bf16* Wfh = wfh + (size_t)l * FFDIM * CDIM;     bf16* Wfl = wfl + (size_t)l * FFDIM * CDIM;
        bf16* Wph = wph + (size_t)l * CDIM * FFDIM;     bf16* Wpl = wpl + (size_t)l * CDIM * FFDIM;

        ln_kernel<<<NTOK, 256>>>(xp, ln1_g + l * CDIM, ln1_b + l * CDIM, hhi, hlo);

        // qkv projection -> bf16 hi/lo
        gemm_tc<false, false, true, false><<<dim3(6, NTOK / 128), 256, GSMEM>>>(
            hhi, hlo, Wqh, Wql, bq, nullptr, nullptr, qvh, qvl, NTOK, 3 * CDIM, CDIM);

        attn_tc<<<dim3(TDIM / 64, BDIM * HEADS), 256, ASMEM>>>(qvh, qvl, yhi, ylo);

        gemm_tc<false, true, false, true><<<dim3(2, NTOK / 128), 256, GSMEM>>>(
            yhi, ylo, Woh, Wol, bo_, xp, xp, nullptr, nullptr, NTOK, CDIM, CDIM);

        ln_kernel<<<NTOK, 256>>>(xp, ln2_g + l * CDIM, ln2_b + l * CDIM, hhi, hlo);

        gemm_tc<true, false, true, false><<<dim3(8, NTOK / 128), 256, GSMEM>>>(
            hhi, hlo, Wfh, Wfl, bf, nullptr, nullptr, fhi, flo, NTOK, FFDIM, CDIM);

        gemm_tc<false, true, false, true><<<dim3(2, NTOK / 128), 256, GSMEM>>>(
            fhi, flo, Wph, Wpl, bp, xp, xp, nullptr, nullptr, NTOK, CDIM, FFDIM);
    }

    ln_kernel<<<NTOK, 256>>>(xp, lnf_g, lnf_b, hhi, hlo);
    gemm_tc<false, false, false, true><<<dim3(1, NTOK / 128), 256, GSMEM>>>(
        hhi, hlo, wlh, wll, nullptr, nullptr, out, nullptr, nullptr, NTOK, VDIM, CDIM);
}

// round 7
// speedup vs baseline: 1.0550x; 1.0550x over previous
#include <cuda_runtime.h>
#include <cuda_bf16.h>
#include <math.h>
#include <stdint.h>

typedef __nv_bfloat16 bf16;

// ---------------- problem dims (gpt-small) ----------------
#define LAYERS 8
#define HEADS  8
#define CDIM   256
#define VDIM   128
#define TDIM   1024
#define BDIM   32
#define FFDIM  1024
#define NTOK   (BDIM*TDIM)   // 32768

// ---------------- scratch (device globals) ----------------
__device__ __align__(128) float g_x  [(size_t)NTOK*CDIM];     // residual stream
__device__ __align__(128) bf16 g_hhi[(size_t)NTOK*CDIM], g_hlo[(size_t)NTOK*CDIM];
__device__ __align__(128) bf16 g_qvh[(size_t)NTOK*3*CDIM], g_qvl[(size_t)NTOK*3*CDIM];
__device__ __align__(128) bf16 g_yhi[(size_t)NTOK*CDIM], g_ylo[(size_t)NTOK*CDIM];
__device__ __align__(128) bf16 g_fhi[(size_t)NTOK*FFDIM], g_flo[(size_t)NTOK*FFDIM];
// transposed + split weights: [N,K] (K-major rows)
__device__ __align__(128) bf16 g_wqh[(size_t)LAYERS*3*CDIM*CDIM], g_wql[(size_t)LAYERS*3*CDIM*CDIM];
__device__ __align__(128) bf16 g_woh[(size_t)LAYERS*CDIM*CDIM],   g_wol[(size_t)LAYERS*CDIM*CDIM];
__device__ __align__(128) bf16 g_wfh[(size_t)LAYERS*FFDIM*CDIM],  g_wfl[(size_t)LAYERS*FFDIM*CDIM];
__device__ __align__(128) bf16 g_wph[(size_t)LAYERS*CDIM*FFDIM],  g_wpl[(size_t)LAYERS*CDIM*FFDIM];
__device__ __align__(128) bf16 g_wlh[(size_t)VDIM*CDIM],          g_wll[(size_t)VDIM*CDIM];

// ---------------- PTX helpers (sm_80-era only) ----------------
__device__ __forceinline__ uint32_t smem_u32(const void* p) {
    uint32_t a;
    asm("{ .reg .u64 t; cvta.to.shared.u64 t, %1; cvt.u32.u64 %0, t; }" : "=r"(a) : "l"(p));
    return a;
}
__device__ __forceinline__ void cp16(uint32_t dst, const void* src) {
    asm volatile("cp.async.cg.shared.global [%0], [%1], 16;" :: "r"(dst), "l"(src));
}
#define CP_COMMIT() asm volatile("cp.async.commit_group;" ::: "memory")
#define CP_WAIT(n)  asm volatile("cp.async.wait_group %0;" :: "n"(n) : "memory")

__device__ __forceinline__ void ldmx4(uint32_t* r, uint32_t addr) {
    asm volatile("ldmatrix.sync.aligned.m8n8.x4.shared.b16 {%0,%1,%2,%3}, [%4];"
        : "=r"(r[0]), "=r"(r[1]), "=r"(r[2]), "=r"(r[3]) : "r"(addr));
}
__device__ __forceinline__ void ldmx4t(uint32_t* r, uint32_t addr) {
    asm volatile("ldmatrix.sync.aligned.m8n8.x4.trans.shared.b16 {%0,%1,%2,%3}, [%4];"
        : "=r"(r[0]), "=r"(r[1]), "=r"(r[2]), "=r"(r[3]) : "r"(addr));
}
__device__ __forceinline__ void mma16816(float* c, const uint32_t* a, const uint32_t* b) {
    asm volatile("mma.sync.aligned.m16n8k16.row.col.f32.bf16.bf16.f32 "
        "{%0,%1,%2,%3}, {%4,%5,%6,%7}, {%8,%9}, {%0,%1,%2,%3};"
        : "+f"(c[0]), "+f"(c[1]), "+f"(c[2]), "+f"(c[3])
        : "r"(a[0]), "r"(a[1]), "r"(a[2]), "r"(a[3]), "r"(b[0]), "r"(b[1]));
}

// ---------------- misc math ----------------
__device__ __forceinline__ float gelu_f(float x) {
    float a = 0.7978845608028654f * (x + 0.044715f * x * x * x);
    a = fminf(fmaxf(a, -15.f), 15.f);
    float e = __expf(2.0f * a);
    float t = (e - 1.0f) / (e + 1.0f);
    return 0.5f * x * (1.0f + t);
}
__device__ __forceinline__ void bf_split(float v, bf16& hi, bf16& lo) {
    hi = __float2bfloat16(v);
    lo = __float2bfloat16(v - __bfloat162float(hi));
}
__device__ __forceinline__ uint32_t pack_hi2(float a, float b) {
    __nv_bfloat162 t; t.x = __float2bfloat16(a); t.y = __float2bfloat16(b);
    return *reinterpret_cast<uint32_t*>(&t);
}
__device__ __forceinline__ uint32_t pack_lo2(float a, float b) {
    bf16 ha = __float2bfloat16(a), hb = __float2bfloat16(b);
    __nv_bfloat162 t;
    t.x = __float2bfloat16(a - __bfloat162float(ha));
    t.y = __float2bfloat16(b - __bfloat162float(hb));
    return *reinterpret_cast<uint32_t*>(&t);
}

// ---------------- embed ----------------
__global__ void embed_kernel(const int* __restrict__ idx,
                             const float* __restrict__ tok,
                             const float* __restrict__ pos,
                             float* __restrict__ x)
{
    int i = blockIdx.x * blockDim.x + threadIdx.x;
    if (i >= NTOK * CDIM) return;
    int c = i & (CDIM - 1);
    int row = i >> 8;
    int t = row & (TDIM - 1);
    x[i] = tok[idx[row] * CDIM + c] + pos[t * CDIM + c];
}

// ---------------- standalone layernorm (only layer-0 ln1) ----------------
__global__ void ln_kernel(const float* __restrict__ x,
                          const float* __restrict__ g,
                          const float* __restrict__ b,
                          bf16* __restrict__ ohi, bf16* __restrict__ olo)
{
    int row = blockIdx.x;
    int c = threadIdx.x;
    float v = x[(size_t)row * CDIM + c];
    float s = v, s2 = v * v;
    #pragma unroll
    for (int o = 16; o; o >>= 1) {
        s  += __shfl_xor_sync(0xffffffffu, s,  o);
        s2 += __shfl_xor_sync(0xffffffffu, s2, o);
    }
    __shared__ float ss[8], ss2[8], m_sh, r_sh;
    int w = c >> 5, lane = c & 31;
    if (lane == 0) { ss[w] = s; ss2[w] = s2; }
    __syncthreads();
    if (c == 0) {
        float S = 0.f, S2 = 0.f;
        #pragma unroll
        for (int i = 0; i < 8; i++) { S += ss[i]; S2 += ss2[i]; }
        float m = S * (1.0f / CDIM);
        float var = S2 * (1.0f / CDIM) - m * m;
        m_sh = m; r_sh = rsqrtf(var + 1e-5f);
    }
    __syncthreads();
    float o = (v - m_sh) * r_sh * g[c] + b[c];
    size_t i = (size_t)row * CDIM + c;
    bf16 hi, lo; bf_split(o, hi, lo);
    ohi[i] = hi; olo[i] = lo;
}

// ---------------- weight transpose + split: W[K,N] -> T[N,K] hi/lo ----------------
__global__ void wsplit_kernel(const float* __restrict__ W,
                              bf16* __restrict__ Thi, bf16* __restrict__ Tlo,
                              int K, int N)
{
    __shared__ float t[32][33];
    int n0 = blockIdx.x << 5, k0 = blockIdx.y << 5;
    int tx = threadIdx.x, ty = threadIdx.y;  // (32,8)
    #pragma unroll
    for (int j = 0; j < 4; j++)
        t[ty + j * 8][tx] = W[(size_t)(k0 + ty + j * 8) * N + n0 + tx];
    __syncthreads();
    #pragma unroll
    for (int j = 0; j < 4; j++) {
        int nl = ty + j * 8;
        float v = t[tx][nl];
        size_t o = (size_t)(n0 + nl) * K + k0 + tx;
        bf16 hi, lo; bf_split(v, hi, lo);
        Thi[o] = hi; Tlo[o] = lo;
    }
}

// ---------------- HMMA split-bf16 GEMM (128x128 tile) ----------------
#define GST   10240
#define STAGE (4*GST)
#define GSMEM (2*STAGE)

__device__ __forceinline__ void g_fill(uint32_t st,
    const bf16* __restrict__ Ahi, const bf16* __restrict__ Alo,
    const bf16* __restrict__ Bhi, const bf16* __restrict__ Blo,
    int row0, int col0, int k0, int K, int tid)
{
    const bf16* base0 = Ahi + (size_t)row0 * K + k0;
    const bf16* base1 = Alo + (size_t)row0 * K + k0;
    const bf16* base2 = Bhi + (size_t)col0 * K + k0;
    const bf16* base3 = Blo + (size_t)col0 * K + k0;
    #pragma unroll
    for (int it = 0; it < 8; it++) {
        int i = tid + (it << 8);
        int mat = i >> 9, j = i & 511;
        int r = j >> 2, ch = j & 3;
        const bf16* src = (mat == 0) ? base0 : (mat == 1) ? base1 : (mat == 2) ? base2 : base3;
        cp16(st + mat * GST + r * 80 + ch * 16, src + (size_t)r * K + ch * 8);
    }
    CP_COMMIT();
}

template<bool GELU_, bool RES_, bool BF16OUT_, bool FP32OUT_>
__global__ void __launch_bounds__(256, 2) gemm_tc(
    const bf16* __restrict__ Ahi, const bf16* __restrict__ Alo,
    const bf16* __restrict__ Bhi, const bf16* __restrict__ Blo,
    const float* __restrict__ bias, const float* __restrict__ res,
    float* __restrict__ Cf, bf16* __restrict__ Chi, bf16* __restrict__ Clo,
    int M, int N, int K)
{
    extern __shared__ char smem[];
    const int tid  = threadIdx.x;
    const int wid  = tid >> 5;
    const int lane = tid & 31;
    const int warpM = wid & 3;
    const int warpN = wid >> 2;
    const int row0 = blockIdx.y << 7;
    const int col0 = blockIdx.x << 7;
    uint32_t sb = smem_u32(smem);

    float acc[2][8][4];
    #pragma unroll
    for (int mt = 0; mt < 2; mt++)
        #pragma unroll
        for (int nt = 0; nt < 8; nt++)
            #pragma unroll
            for (int j = 0; j < 4; j++) acc[mt][nt][j] = 0.f;

    const int nk = K >> 5;
    g_fill(sb, Ahi, Alo, Bhi, Blo, row0, col0, 0, K, tid);

    const uint32_t aoff_base = (uint32_t)((warpM * 32 + (lane & 15)) * 80 + ((lane >> 4) & 1) * 16);
    const uint32_t boff_base = (uint32_t)((warpN * 64 + ((lane >> 4) & 1) * 8 + (lane & 7)) * 80
                                          + ((lane >> 3) & 1) * 16);

    for (int kt = 0; kt < nk; kt++) {
        uint32_t st = sb + (uint32_t)(kt & 1) * STAGE;
        if (kt + 1 < nk) {
            g_fill(sb + (uint32_t)((kt + 1) & 1) * STAGE, Ahi, Alo, Bhi, Blo,
                   row0, col0, (kt + 1) << 5, K, tid);
            CP_WAIT(1);
        } else {
            CP_WAIT(0);
        }
        __syncthreads();

        #pragma unroll
        for (int k16 = 0; k16 < 2; k16++) {
            uint32_t ka = st + aoff_base + k16 * 32;
            uint32_t kb = st + boff_base + k16 * 32;
            uint32_t ah[2][4], al[2][4], bh[4][4], bl[4][4];
            ldmx4(ah[0], ka);
            ldmx4(ah[1], ka + 16 * 80);
            ldmx4(al[0], ka + GST);
            ldmx4(al[1], ka + GST + 16 * 80);
            #pragma unroll
            for (int nt2 = 0; nt2 < 4; nt2++) {
                ldmx4(bh[nt2], kb + 2 * GST + nt2 * (16 * 80));
                ldmx4(bl[nt2], kb + 3 * GST + nt2 * (16 * 80));
            }
            #pragma unroll
            for (int mt = 0; mt < 2; mt++)
                #pragma unroll
                for (int nt = 0; nt < 8; nt++) {
                    const uint32_t* bhp = &bh[nt >> 1][(nt & 1) * 2];
                    const uint32_t* blp = &bl[nt >> 1][(nt & 1) * 2];
                    mma16816(acc[mt][nt], ah[mt], bhp);
                    mma16816(acc[mt][nt], ah[mt], blp);
                    mma16816(acc[mt][nt], al[mt], bhp);
                }
        }
        __syncthreads();
    }

    const int g  = lane >> 2;
    const int tg = lane & 3;
    #pragma unroll
    for (int mt = 0; mt < 2; mt++) {
        #pragma unroll
        for (int half = 0; half < 2; half++) {
            int m = row0 + warpM * 32 + mt * 16 + g + half * 8;
            #pragma unroll
            for (int nt = 0; nt < 8; nt++) {
                int col = col0 + warpN * 64 + nt * 8 + tg * 2;
                float v0 = acc[mt][nt][half * 2 + 0];
                float v1 = acc[mt][nt][half * 2 + 1];
                if (bias) { v0 += bias[col]; v1 += bias[col + 1]; }
                if (GELU_) { v0 = gelu_f(v0); v1 = gelu_f(v1); }
                size_t o = (size_t)m * N + col;
                if (RES_) {
                    float2 r2 = *reinterpret_cast<const float2*>(&res[o]);
                    v0 += r2.x; v1 += r2.y;
                }
                if (FP32OUT_) {
                    *reinterpret_cast<float2*>(&Cf[o]) = make_float2(v0, v1);
                }
                if (BF16OUT_) {
                    bf16 h0, l0, h1, l1;
                    bf_split(v0, h0, l0); bf_split(v1, h1, l1);
                    __nv_bfloat162 hh; hh.x = h0; hh.y = h1;
                    __nv_bfloat162 ll; ll.x = l0; ll.y = l1;
                    *reinterpret_cast<__nv_bfloat162*>(&Chi[o]) = hh;
                    *reinterpret_cast<__nv_bfloat162*>(&Clo[o]) = ll;
                }
            }
        }
    }
}

// ---------------- fused GEMM + residual + LayerNorm (128x256 tile, 512 thr) ----
// C = A @ B^T + bias;  x_new = C + x_old (written);  h = LN(x_new) hi/lo (written)
#define FST_A 10240          // 128 rows * 80
#define FST_B 20480          // 256 rows * 80
#define FSTAGE (2*FST_A + 2*FST_B)   // 61440
#define FRED  (2*FSTAGE)             // reduce scratch offset
#define FSMEM (2*FSTAGE + 1024)      // + rsum[128], rsq[128]

__device__ __forceinline__ void f_fill(uint32_t st,
    const bf16* __restrict__ Ahi, const bf16* __restrict__ Alo,
    const bf16* __restrict__ Bhi, const bf16* __restrict__ Blo,
    int row0, int k0, int K, int tid)
{
    const bf16* a0 = Ahi + (size_t)row0 * K + k0;
    const bf16* a1 = Alo + (size_t)row0 * K + k0;
    const bf16* b0 = Bhi + k0;
    const bf16* b1 = Blo + k0;
    #pragma unroll
    for (int it = 0; it < 6; it++) {
        int i = tid + it * 512;
        if (i < 1024) {
            int mat = i >> 9, j = i & 511, r = j >> 2, ch = j & 3;
            const bf16* src = mat ? a1 : a0;
            cp16(st + mat * FST_A + r * 80 + ch * 16, src + (size_t)r * K + ch * 8);
        } else {
            int i2 = i - 1024;
            int mat = i2 >> 10, j = i2 & 1023, r = j >> 2, ch = j & 3;
            const bf16* src = mat ? b1 : b0;
            cp16(st + 2 * FST_A + mat * FST_B + r * 80 + ch * 16, src + (size_t)r * K + ch * 8);
        }
    }
    CP_COMMIT();
}

__global__ void __launch_bounds__(512, 1) gemm_fused_ln(
    const bf16* __restrict__ Ahi, const bf16* __restrict__ Alo,
    const bf16* __restrict__ Bhi, const bf16* __restrict__ Blo,
    const float* __restrict__ bias,
    float* __restrict__ x,                       // residual in/out
    const float* __restrict__ lng, const float* __restrict__ lnb,
    bf16* __restrict__ Chi, bf16* __restrict__ Clo,
    int K)
{
    extern __shared__ char smem[];
    const int tid  = threadIdx.x;
    const int wid  = tid >> 5;
    const int lane = tid & 31;
    const int warpM = wid & 3;       // 4 row groups of 32
    const int warpN = wid >> 2;      // 4 col groups of 64
    const int row0 = blockIdx.y << 7;
    uint32_t sb = smem_u32(smem);
    float* rsum = (float*)(smem + FRED);
    float* rsq  = (float*)(smem + FRED + 512);

    if (tid < 128) { rsum[tid] = 0.f; rsq[tid] = 0.f; }

    float acc[2][8][4];
    #pragma unroll
    for (int mt = 0; mt < 2; mt++)
        #pragma unroll
        for (int nt = 0; nt < 8; nt++)
            #pragma unroll
            for (int j = 0; j < 4; j++) acc[mt][nt][j] = 0.f;

    const int nk = K >> 5;
    f_fill(sb, Ahi, Alo, Bhi, Blo, row0, 0, K, tid);

    const uint32_t aoff = (uint32_t)((warpM * 32 + (lane & 15)) * 80 + ((lane >> 4) & 1) * 16);
    const uint32_t boff = (uint32_t)(2 * FST_A
                         + (warpN * 64 + ((lane >> 4) & 1) * 8 + (lane & 7)) * 80
                         + ((lane >> 3) & 1) * 16);

    for (int kt = 0; kt < nk; kt++) {
        uint32_t st = sb + (uint32_t)(kt & 1) * FSTAGE;
        if (kt + 1 < nk) {
            f_fill(sb + (uint32_t)((kt + 1) & 1) * FSTAGE, Ahi, Alo, Bhi, Blo,
                   row0, (kt + 1) << 5, K, tid);
            CP_WAIT(1);
        } else {
            CP_WAIT(0);
        }
        __syncthreads();

        #pragma unroll
        for (int k16 = 0; k16 < 2; k16++) {
            uint32_t ka = st + aoff + k16 * 32;
            uint32_t kb = st + boff + k16 * 32;
            uint32_t ah[2][4], al[2][4], bh[4][4], bl[4][4];
            ldmx4(ah[0], ka);
            ldmx4(ah[1], ka + 16 * 80);
            ldmx4(al[0], ka + FST_A);
            ldmx4(al[1], ka + FST_A + 16 * 80);
            #pragma unroll
            for (int nt2 = 0; nt2 < 4; nt2++) {
                ldmx4(bh[nt2], kb + nt2 * (16 * 80));
                ldmx4(bl[nt2], kb + FST_B + nt2 * (16 * 80));
            }
            #pragma unroll
            for (int mt = 0; mt < 2; mt++)
                #pragma unroll
                for (int nt = 0; nt < 8; nt++) {
                    const uint32_t* bhp = &bh[nt >> 1][(nt & 1) * 2];
                    const uint32_t* blp = &bl[nt >> 1][(nt & 1) * 2];
                    mma16816(acc[mt][nt], ah[mt], bhp);
                    mma16816(acc[mt][nt], ah[mt], blp);
                    mma16816(acc[mt][nt], al[mt], bhp);
                }
        }
        __syncthreads();
    }

    // ---- epilogue: bias + residual, row stats, LN, writes ----
    const int g  = lane >> 2;
    const int tg = lane & 3;
    // pass 1: bias + residual into acc; accumulate row sums
    #pragma unroll
    for (int mt = 0; mt < 2; mt++) {
        #pragma unroll
        for (int half = 0; half < 2; half++) {
            int ml = warpM * 32 + mt * 16 + g + half * 8;
            int m = row0 + ml;
            float s = 0.f, s2 = 0.f;
            #pragma unroll
            for (int nt = 0; nt < 8; nt++) {
                int col = warpN * 64 + nt * 8 + tg * 2;
                float v0 = acc[mt][nt][half * 2 + 0] + bias[col];
                float v1 = acc[mt][nt][half * 2 + 1] + bias[col + 1];
                float2 r2 = *reinterpret_cast<const float2*>(&x[(size_t)m * CDIM + col]);
                v0 += r2.x; v1 += r2.y;
                acc[mt][nt][half * 2 + 0] = v0;
                acc[mt][nt][half * 2 + 1] = v1;
                s += v0 + v1;
                s2 += v0 * v0 + v1 * v1;
            }
            s  += __shfl_xor_sync(0xffffffffu, s, 1);
            s  += __shfl_xor_sync(0xffffffffu, s, 2);
            s2 += __shfl_xor_sync(0xffffffffu, s2, 1);
            s2 += __shfl_xor_sync(0xffffffffu, s2, 2);
            if (tg == 0) {
                atomicAdd(&rsum[ml], s);
                atomicAdd(&rsq[ml], s2);
            }
        }
    }
    __syncthreads();
    if (tid < 128) {
        float m = rsum[tid] * (1.0f / CDIM);
        float var = rsq[tid] * (1.0f / CDIM) - m * m;
        rsum[tid] = m;
        rsq[tid]  = rsqrtf(var + 1e-5f);
    }
    __syncthreads();
    // pass 2: write x and LN'd hi/lo
    #pragma unroll
    for (int mt = 0; mt < 2; mt++) {
        #pragma unroll
        for (int half = 0; half < 2; half++) {
            int ml = warpM * 32 + mt * 16 + g + half * 8;
            int m = row0 + ml;
            float mu = rsum[ml], rst = rsq[ml];
            #pragma unroll
            for (int nt = 0; nt < 8; nt++) {
                int col = warpN * 64 + nt * 8 + tg * 2;
                float v0 = acc[mt][nt][half * 2 + 0];
                float v1 = acc[mt][nt][half * 2 + 1];
                size_t o = (size_t)m * CDIM + col;
                *reinterpret_cast<float2*>(&x[o]) = make_float2(v0, v1);
                float h0 = (v0 - mu) * rst * lng[col] + lnb[col];
                float h1 = (v1 - mu) * rst * lng[col + 1] + lnb[col + 1];
                bf16 a0, b0, a1, b1;
                bf_split(h0, a0, b0); bf_split(h1, a1, b1);
                __nv_bfloat162 hh; hh.x = a0; hh.y = a1;
                __nv_bfloat162 ll; ll.x = b0; ll.y = b1;
                *reinterpret_cast<__nv_bfloat162*>(&Chi[o]) = hh;
                *reinterpret_cast<__nv_bfloat162*>(&Clo[o]) = ll;
            }
        }
    }
}

// ================= HMMA flash attention (unchanged from R5) =================
#define AQ_HI 0
#define AQ_LO 5120
#define ASTG  10240
#define ASTGSZ 20480
#define ARMAX 51200
#define ARSUM 51712
#define ALINV 52224
#define ASMEM 52480
#define ASCALE 0.17677669529663687f

__device__ __forceinline__ void a_fill_kv(uint32_t dst, const bf16* __restrict__ qh,
                                          const bf16* __restrict__ ql,
                                          size_t tokbase, int hcol, int k0, int tid)
{
    int r = tid >> 2, ch = tid & 3;
    size_t rowoff = tokbase + (size_t)(k0 + r) * 768;
    uint32_t so = (uint32_t)(r * 80 + ch * 16);
    cp16(dst + so,         qh + rowoff + 256 + hcol + ch * 8);
    cp16(dst + 5120 + so,  ql + rowoff + 256 + hcol + ch * 8);
    cp16(dst + 10240 + so, qh + rowoff + 512 + hcol + ch * 8);
    cp16(dst + 15360 + so, ql + rowoff + 512 + hcol + ch * 8);
}

__global__ void __launch_bounds__(256, 1) attn_tc(
    const bf16* __restrict__ qh, const bf16* __restrict__ ql,
    bf16* __restrict__ yhi, bf16* __restrict__ ylo)
{
    extern __shared__ char smem[];
    uint32_t sb = smem_u32(smem);
    const int tid = threadIdx.x, wid = tid >> 5, lane = tid & 31;
    const int warpM = wid & 3, warpN = wid >> 2;
    const int g = lane >> 2, tg = lane & 3;
    const int qt = (int)gridDim.x - 1 - (int)blockIdx.x;
    const int bh = blockIdx.y;
    const int b = bh >> 3, h = bh & 7;
    const int q0 = qt * 64, hcol = h * 32;
    const size_t tokbase = (size_t)b * TDIM * 768;

    {
        int r = tid >> 2, ch = tid & 3;
        size_t qoff = tokbase + (size_t)(q0 + r) * 768 + hcol + ch * 8;
        uint32_t so = (uint32_t)(r * 80 + ch * 16);
        cp16(sb + AQ_HI + so, qh + qoff);
        cp16(sb + AQ_LO + so, ql + qoff);
    }
    a_fill_kv(sb + ASTG, qh, ql, tokbase, hcol, 0, tid);
    CP_COMMIT();

    const int r0 = warpM * 16 + g, r1 = r0 + 8;
    float m0 = -1e30f, m1 = -1e30f, l0 = 0.f, l1 = 0.f;
    float oc[4][4];
    #pragma unroll
    for (int n = 0; n < 4; n++)
        #pragma unroll
        for (int j = 0; j < 4; j++) oc[n][j] = 0.f;

    const uint32_t qa = sb + AQ_HI + (uint32_t)((warpM * 16 + (lane & 15)) * 80 + ((lane >> 4) & 1) * 16);
    const uint32_t kboff = (uint32_t)((warpN * 32 + ((lane >> 4) & 1) * 8 + (lane & 7)) * 80
                                      + ((lane >> 3) & 1) * 16);
    const uint32_t vaoff = (uint32_t)((warpN * 32 + (lane & 15)) * 80 + ((lane >> 4) & 1) * 16);

    float* rmax = (float*)(smem + ARMAX);
    float* rsum = (float*)(smem + ARSUM);
    float* linv = (float*)(smem + ALINV);

    for (int kt = 0; kt <= qt; kt++) {
        CP_WAIT(0);
        __syncthreads();
        uint32_t stg = sb + ASTG + (uint32_t)(kt & 1) * ASTGSZ;

        float sc[4][4];
        #pragma unroll
        for (int n = 0; n < 4; n++)
            #pragma unroll
            for (int j = 0; j < 4; j++) sc[n][j] = 0.f;

        #pragma unroll
        for (int k16 = 0; k16 < 2; k16++) {
            uint32_t ah[4], al[4], bhh[2][4], bll[2][4];
            ldmx4(ah, qa + k16 * 32);
            ldmx4(al, qa + 5120 + k16 * 32);
            ldmx4(bhh[0], stg + kboff + k16 * 32);
            ldmx4(bhh[1], stg + kboff + k16 * 32 + 16 * 80);
            ldmx4(bll[0], stg + 5120 + kboff + k16 * 32);
            ldmx4(bll[1], stg + 5120 + kboff + k16 * 32 + 16 * 80);
            #pragma unroll
            for (int n = 0; n < 4; n++) {
                const uint32_t* bp = &bhh[n >> 1][(n & 1) * 2];
                const uint32_t* lp = &bll[n >> 1][(n & 1) * 2];
                mma16816(sc[n], ah, bp);
                mma16816(sc[n], ah, lp);
                mma16816(sc[n], al, bp);
            }
        }

        const bool diag = (kt == qt);
        #pragma unroll
        for (int n = 0; n < 4; n++)
            #pragma unroll
            for (int j = 0; j < 4; j++) {
                float s = sc[n][j] * ASCALE;
                if (diag) {
                    int kc = warpN * 32 + n * 8 + tg * 2 + (j & 1);
                    int qr = (j < 2) ? r0 : r1;
                    if (kc > qr) s = -1e30f;
                }
                sc[n][j] = s;
            }

        float mx0 = -1e30f, mx1 = -1e30f;
        #pragma unroll
        for (int n = 0; n < 4; n++) {
            mx0 = fmaxf(mx0, fmaxf(sc[n][0], sc[n][1]));
            mx1 = fmaxf(mx1, fmaxf(sc[n][2], sc[n][3]));
        }
        mx0 = fmaxf(mx0, __shfl_xor_sync(0xffffffffu, mx0, 1));
        mx0 = fmaxf(mx0, __shfl_xor_sync(0xffffffffu, mx0, 2));
        mx1 = fmaxf(mx1, __shfl_xor_sync(0xffffffffu, mx1, 1));
        mx1 = fmaxf(mx1, __shfl_xor_sync(0xffffffffu, mx1, 2));
        if (tg == 0) { rmax[warpN * 64 + r0] = mx0; rmax[warpN * 64 + r1] = mx1; }
        __syncthreads();

        if (kt < qt) {
            a_fill_kv(sb + ASTG + (uint32_t)((kt + 1) & 1) * ASTGSZ,
                      qh, ql, tokbase, hcol, (kt + 1) * 64, tid);
            CP_COMMIT();
        }

        float M0 = fmaxf(rmax[r0], rmax[64 + r0]);
        float M1 = fmaxf(rmax[r1], rmax[64 + r1]);
        float n0 = fmaxf(m0, M0), n1 = fmaxf(m1, M1);
        float al0 = __expf(m0 - n0), al1 = __expf(m1 - n1);

        float s0 = 0.f, s1 = 0.f;
        #pragma unroll
        for (int n = 0; n < 4; n++) {
            #pragma unroll
            for (int j = 0; j < 4; j++) {
                float mn = (j < 2) ? n0 : n1;
                float p = __expf(sc[n][j] - mn);
                sc[n][j] = p;
                if (j < 2) s0 += p; else s1 += p;
            }
        }
        s0 += __shfl_xor_sync(0xffffffffu, s0, 1);
        s0 += __shfl_xor_sync(0xffffffffu, s0, 2);
        s1 += __shfl_xor_sync(0xffffffffu, s1, 1);
        s1 += __shfl_xor_sync(0xffffffffu, s1, 2);
        if (tg == 0) { rsum[warpN * 64 + r0] = s0; rsum[warpN * 64 + r1] = s1; }

        uint32_t ph[2][4], pl[2][4];
        #pragma unroll
        for (int t = 0; t < 2; t++) {
            ph[t][0] = pack_hi2(sc[2*t][0],   sc[2*t][1]);
            ph[t][1] = pack_hi2(sc[2*t][2],   sc[2*t][3]);
            ph[t][2] = pack_hi2(sc[2*t+1][0], sc[2*t+1][1]);
            ph[t][3] = pack_hi2(sc[2*t+1][2], sc[2*t+1][3]);
            pl[t][0] = pack_lo2(sc[2*t][0],   sc[2*t][1]);
            pl[t][1] = pack_lo2(sc[2*t][2],   sc[2*t][3]);
            pl[t][2] = pack_lo2(sc[2*t+1][0], sc[2*t+1][1]);
            pl[t][3] = pack_lo2(sc[2*t+1][2], sc[2*t+1][3]);
        }
        __syncthreads();
        float S0 = rsum[r0] + rsum[64 + r0];
        float S1 = rsum[r1] + rsum[64 + r1];
        l0 = l0 * al0 + S0; l1 = l1 * al1 + S1;
        m0 = n0; m1 = n1;
        #pragma unroll
        for (int n = 0; n < 4; n++) {
            oc[n][0] *= al0; oc[n][1] *= al0;
            oc[n][2] *= al1; oc[n][3] *= al1;
        }

        #pragma unroll
        for (int t = 0; t < 2; t++) {
            uint32_t va = stg + 10240 + vaoff + (uint32_t)t * (16 * 80);
            uint32_t vh0[4], vh1[4], vl0[4], vl1[4];
            ldmx4t(vh0, va);
            ldmx4t(vh1, va + 32);
            ldmx4t(vl0, va + 5120);
            ldmx4t(vl1, va + 5120 + 32);
            #pragma unroll
            for (int n = 0; n < 4; n++) {
                const uint32_t* bp = (n < 2) ? &vh0[(n & 1) * 2] : &vh1[(n & 1) * 2];
                const uint32_t* lp = (n < 2) ? &vl0[(n & 1) * 2] : &vl1[(n & 1) * 2];
                mma16816(oc[n], ph[t], bp);
                mma16816(oc[n], pl[t], bp);
                mma16816(oc[n], ph[t], lp);
            }
        }
    }

    __syncthreads();
    float* osum = (float*)(smem + ASTG);
    if (warpN == 0) {
        #pragma unroll
        for (int n = 0; n < 4; n++)
            #pragma unroll
            for (int j = 0; j < 4; j++) {
                int rr = (j < 2) ? r0 : r1;
                int cc = n * 8 + tg * 2 + (j & 1);
                osum[rr * 33 + cc] = oc[n][j];
            }
    }
    if (warpN == 0 && tg == 0) { linv[r0] = 1.f / l0; linv[r1] = 1.f / l1; }
    __syncthreads();
    if (warpN == 1) {
        #pragma unroll
        for (int n = 0; n < 4; n++)
            #pragma unroll
            for (int j = 0; j < 4; j++) {
                int rr = (j < 2) ? r0 : r1;
                int cc = n * 8 + tg * 2 + (j & 1);
                osum[rr * 33 + cc] += oc[n][j];
            }
    }
    __syncthreads();
    {
        int row = tid >> 2, cg = tid & 3;
        float il = linv[row];
        size_t gout = (size_t)(b * TDIM + q0 + row) * CDIM + hcol + cg * 8;
        #pragma unroll
        for (int jp = 0; jp < 4; jp++) {
            float v0 = osum[row * 33 + cg * 8 + jp * 2]     * il;
            float v1 = osum[row * 33 + cg * 8 + jp * 2 + 1] * il;
            bf16 h0, lo0, h1, lo1;
            bf_split(v0, h0, lo0); bf_split(v1, h1, lo1);
            __nv_bfloat162 hh; hh.x = h0; hh.y = h1;
            __nv_bfloat162 ll; ll.x = lo0; ll.y = lo1;
            *reinterpret_cast<__nv_bfloat162*>(&yhi[gout + jp * 2]) = hh;
            *reinterpret_cast<__nv_bfloat162*>(&ylo[gout + jp * 2]) = ll;
        }
    }
}

// ---------------- host orchestration ----------------
extern "C" void kernel_launch(void* const* d_in, const int* in_sizes, int n_in,
                              void* d_out, int out_size)
{
    const int*   idx     = (const int*)  d_in[0];
    const float* tok_emb = (const float*)d_in[1];
    const float* pos_emb = (const float*)d_in[2];
    const float* ln1_g   = (const float*)d_in[3];
    const float* ln1_b   = (const float*)d_in[4];
    const float* wqkv    = (const float*)d_in[5];
    const float* bqkv    = (const float*)d_in[6];
    const float* wo      = (const float*)d_in[7];
    const float* bo      = (const float*)d_in[8];
    const float* ln2_g   = (const float*)d_in[9];
    const float* ln2_b   = (const float*)d_in[10];
    const float* wfc     = (const float*)d_in[11];
    const float* bfc     = (const float*)d_in[12];
    const float* wpr     = (const float*)d_in[13];
    const float* bpr     = (const float*)d_in[14];
    const float* lnf_g   = (const float*)d_in[15];
    const float* lnf_b   = (const float*)d_in[16];
    const float* w_lm    = (const float*)d_in[17];
    float* out = (float*)d_out;

    float *xp;
    bf16 *hhi, *hlo, *qvh, *qvl, *yhi, *ylo, *fhi, *flo;
    bf16 *wqh, *wql, *woh, *wol, *wfh, *wfl, *wph, *wpl, *wlh, *wll;
    cudaGetSymbolAddress((void**)&xp,   g_x);
    cudaGetSymbolAddress((void**)&hhi,  g_hhi);  cudaGetSymbolAddress((void**)&hlo, g_hlo);
    cudaGetSymbolAddress((void**)&qvh,  g_qvh);  cudaGetSymbolAddress((void**)&qvl, g_qvl);
    cudaGetSymbolAddress((void**)&yhi,  g_yhi);  cudaGetSymbolAddress((void**)&ylo, g_ylo);
    cudaGetSymbolAddress((void**)&fhi,  g_fhi);  cudaGetSymbolAddress((void**)&flo, g_flo);
    cudaGetSymbolAddress((void**)&wqh,  g_wqh);  cudaGetSymbolAddress((void**)&wql, g_wql);
    cudaGetSymbolAddress((void**)&woh,  g_woh);  cudaGetSymbolAddress((void**)&wol, g_wol);
    cudaGetSymbolAddress((void**)&wfh,  g_wfh);  cudaGetSymbolAddress((void**)&wfl, g_wfl);
    cudaGetSymbolAddress((void**)&wph,  g_wph);  cudaGetSymbolAddress((void**)&wpl, g_wpl);
    cudaGetSymbolAddress((void**)&wlh,  g_wlh);  cudaGetSymbolAddress((void**)&wll, g_wll);

    cudaFuncSetAttribute(gemm_tc<false, false, false, true>,
                         cudaFuncAttributeMaxDynamicSharedMemorySize, GSMEM);
    cudaFuncSetAttribute(gemm_tc<true, false, true, false>,
                         cudaFuncAttributeMaxDynamicSharedMemorySize, GSMEM);
    cudaFuncSetAttribute(gemm_tc<false, false, true, false>,
                         cudaFuncAttributeMaxDynamicSharedMemorySize, GSMEM);
    cudaFuncSetAttribute(gemm_fused_ln,
                         cudaFuncAttributeMaxDynamicSharedMemorySize, FSMEM);
    cudaFuncSetAttribute(attn_tc,
                         cudaFuncAttributeMaxDynamicSharedMemorySize, ASMEM);

    // ---- weight prep (transpose + bf16 split) ----
    dim3 wb(32, 8);
    for (int l = 0; l < LAYERS; l++) {
        wsplit_kernel<<<dim3(24, 8), wb>>>(wqkv + (size_t)l * CDIM * 3 * CDIM,
                                           wqh + (size_t)l * 3 * CDIM * CDIM,
                                           wql + (size_t)l * 3 * CDIM * CDIM, CDIM, 3 * CDIM);
        wsplit_kernel<<<dim3(8, 8),  wb>>>(wo + (size_t)l * CDIM * CDIM,
                                           woh + (size_t)l * CDIM * CDIM,
                                           wol + (size_t)l * CDIM * CDIM, CDIM, CDIM);
        wsplit_kernel<<<dim3(32, 8), wb>>>(wfc + (size_t)l * CDIM * FFDIM,
                                           wfh + (size_t)l * FFDIM * CDIM,
                                           wfl + (size_t)l * FFDIM * CDIM, CDIM, FFDIM);
        wsplit_kernel<<<dim3(8, 32), wb>>>(wpr + (size_t)l * FFDIM * CDIM,
                                           wph + (size_t)l * CDIM * FFDIM,
                                           wpl + (size_t)l * CDIM * FFDIM, FFDIM, CDIM);
    }
    wsplit_kernel<<<dim3(4, 8), wb>>>(w_lm, wlh, wll, CDIM, VDIM);

    embed_kernel<<<(NTOK * CDIM + 255) / 256, 256>>>(idx, tok_emb, pos_emb, xp);
    // layer-0 ln1 (all later LNs are fused into GEMM epilogues)
    ln_kernel<<<NTOK, 256>>>(xp, ln1_g, ln1_b, hhi, hlo);

    for (int l = 0; l < LAYERS; l++) {
        const float* bq  = bqkv + (size_t)l * 3 * CDIM;
        const float* bo_ = bo   + (size_t)l * CDIM;
        const float* bf  = bfc  + (size_t)l * FFDIM;
        const float* bp  = bpr  + (size_t)l * CDIM;
        bf16* Wqh = wqh + (size_t)l * 3 * CDIM * CDIM;  bf16* Wql = wql + (size_t)l * 3 * CDIM * CDIM;
        bf16* Woh = woh + (size_t)l * CDIM * CDIM;      bf16* Wol = wol + (size_t)l * CDIM * CDIM;
        bf16* Wfh = wfh + (size_t)l * FFDIM * CDIM;     bf16* Wfl = wfl + (size_t)l * FFDIM * CDIM;
        bf16* Wph = wph + (size_t)l * CDIM * FFDIM;     bf16* Wpl = wpl + (size_t)l * CDIM * FFDIM;

        // qkv projection -> bf16 hi/lo
        gemm_tc<false, false, true, false><<<dim3(6, NTOK / 128), 256, GSMEM>>>(
            hhi, hlo, Wqh, Wql, bq, nullptr, nullptr, qvh, qvl, NTOK, 3 * CDIM, CDIM);

        attn_tc<<<dim3(TDIM / 64, BDIM * HEADS), 256, ASMEM>>>(qvh, qvl, yhi, ylo);

        // attn out proj + residual + fused ln2 -> h
        gemm_fused_ln<<<dim3(1, NTOK / 128), 512, FSMEM>>>(
            yhi, ylo, Woh, Wol, bo_, xp,
            ln2_g + (size_t)l * CDIM, ln2_b + (size_t)l * CDIM, hhi, hlo, CDIM);

        // fc + gelu
        gemm_tc<true, false, true, false><<<dim3(8, NTOK / 128), 256, GSMEM>>>(
            hhi, hlo, Wfh, Wfl, bf, nullptr, nullptr, fhi, flo, NTOK, FFDIM, CDIM);

        // mlp proj + residual + fused (next ln1 | lnf) -> h
        const float* ng = (l + 1 < LAYERS) ? ln1_g + (size_t)(l + 1) * CDIM : lnf_g;
        const float* nb = (l + 1 < LAYERS) ? ln1_b + (size_t)(l + 1) * CDIM : lnf_b;
        gemm_fused_ln<<<dim3(1, NTOK / 128), 512, FSMEM>>>(
            fhi, flo, Wph, Wpl, bp, xp, ng, nb, hhi, hlo, FFDIM);
    }

    // lm head (h already = LN_f(x))
    gemm_tc<false, false, false, true><<<dim3(1, NTOK / 128), 256, GSMEM>>>(
        hhi, hlo, wlh, wll, nullptr, nullptr, out, nullptr, nullptr, NTOK, VDIM, CDIM);
}

// round 9
// speedup vs baseline: 1.1549x; 1.0947x over previous
#include <cuda_runtime.h>
#include <cuda_bf16.h>
#include <math.h>
#include <stdint.h>

typedef __nv_bfloat16 bf16;

// ---------------- problem dims (gpt-small) ----------------
#define LAYERS 8
#define HEADS  8
#define CDIM   256
#define VDIM   128
#define TDIM   1024
#define BDIM   32
#define FFDIM  1024
#define NTOK   (BDIM*TDIM)   // 32768

// ---------------- scratch (device globals) ----------------
__device__ __align__(128) float g_x  [(size_t)NTOK*CDIM];     // residual stream
__device__ __align__(128) bf16 g_hhi[(size_t)NTOK*CDIM], g_hlo[(size_t)NTOK*CDIM];
__device__ __align__(128) bf16 g_qvh[(size_t)NTOK*3*CDIM], g_qvl[(size_t)NTOK*3*CDIM];
__device__ __align__(128) bf16 g_yhi[(size_t)NTOK*CDIM], g_ylo[(size_t)NTOK*CDIM];
__device__ __align__(128) bf16 g_fhi[(size_t)NTOK*FFDIM], g_flo[(size_t)NTOK*FFDIM];
// transposed + split weights: [N,K] (K-major rows)
__device__ __align__(128) bf16 g_wqh[(size_t)LAYERS*3*CDIM*CDIM], g_wql[(size_t)LAYERS*3*CDIM*CDIM];
__device__ __align__(128) bf16 g_woh[(size_t)LAYERS*CDIM*CDIM],   g_wol[(size_t)LAYERS*CDIM*CDIM];
__device__ __align__(128) bf16 g_wfh[(size_t)LAYERS*FFDIM*CDIM],  g_wfl[(size_t)LAYERS*FFDIM*CDIM];
__device__ __align__(128) bf16 g_wph[(size_t)LAYERS*CDIM*FFDIM],  g_wpl[(size_t)LAYERS*CDIM*FFDIM];
__device__ __align__(128) bf16 g_wlh[(size_t)VDIM*CDIM],          g_wll[(size_t)VDIM*CDIM];

// ---------------- PTX helpers (sm_80-era only) ----------------
__device__ __forceinline__ uint32_t smem_u32(const void* p) {
    uint32_t a;
    asm("{ .reg .u64 t; cvta.to.shared.u64 t, %1; cvt.u32.u64 %0, t; }" : "=r"(a) : "l"(p));
    return a;
}
__device__ __forceinline__ void cp16(uint32_t dst, const void* src) {
    asm volatile("cp.async.cg.shared.global [%0], [%1], 16;" :: "r"(dst), "l"(src));
}
#define CP_COMMIT() asm volatile("cp.async.commit_group;" ::: "memory")
#define CP_WAIT(n)  asm volatile("cp.async.wait_group %0;" :: "n"(n) : "memory")

__device__ __forceinline__ void ldmx4(uint32_t* r, uint32_t addr) {
    asm volatile("ldmatrix.sync.aligned.m8n8.x4.shared.b16 {%0,%1,%2,%3}, [%4];"
        : "=r"(r[0]), "=r"(r[1]), "=r"(r[2]), "=r"(r[3]) : "r"(addr));
}
__device__ __forceinline__ void ldmx4t(uint32_t* r, uint32_t addr) {
    asm volatile("ldmatrix.sync.aligned.m8n8.x4.trans.shared.b16 {%0,%1,%2,%3}, [%4];"
        : "=r"(r[0]), "=r"(r[1]), "=r"(r[2]), "=r"(r[3]) : "r"(addr));
}
__device__ __forceinline__ void mma16816(float* c, const uint32_t* a, const uint32_t* b) {
    asm volatile("mma.sync.aligned.m16n8k16.row.col.f32.bf16.bf16.f32 "
        "{%0,%1,%2,%3}, {%4,%5,%6,%7}, {%8,%9}, {%0,%1,%2,%3};"
        : "+f"(c[0]), "+f"(c[1]), "+f"(c[2]), "+f"(c[3])
        : "r"(a[0]), "r"(a[1]), "r"(a[2]), "r"(a[3]), "r"(b[0]), "r"(b[1]));
}
__device__ __forceinline__ uint32_t cvt2(float a, float b) {   // {x=a, y=b}
    uint32_t r;
    asm("cvt.rn.bf16x2.f32 %0, %1, %2;" : "=r"(r) : "f"(b), "f"(a));
    return r;
}
// split two floats -> packed bf16x2 hi + bf16x2 lo (fast path)
__device__ __forceinline__ void pack2(float a, float b, uint32_t& hi, uint32_t& lo) {
    uint32_t h = cvt2(a, b);
    float ha = __uint_as_float(h << 16);
    float hb = __uint_as_float(h & 0xffff0000u);
    lo = cvt2(a - ha, b - hb);
    hi = h;
}

// ---------------- misc math ----------------
__device__ __forceinline__ float gelu_f(float x) {
    float a = 0.7978845608028654f * (x + 0.044715f * x * x * x);
    a = fminf(fmaxf(a, -15.f), 15.f);
    float e = __expf(2.0f * a);
    float t = (e - 1.0f) / (e + 1.0f);
    return 0.5f * x * (1.0f + t);
}
__device__ __forceinline__ void bf_split(float v, bf16& hi, bf16& lo) {
    hi = __float2bfloat16(v);
    lo = __float2bfloat16(v - __bfloat162float(hi));
}

// ---------------- embed ----------------
__global__ void embed_kernel(const int* __restrict__ idx,
                             const float* __restrict__ tok,
                             const float* __restrict__ pos,
                             float* __restrict__ x)
{
    int i = blockIdx.x * blockDim.x + threadIdx.x;
    if (i >= NTOK * CDIM) return;
    int c = i & (CDIM - 1);
    int row = i >> 8;
    int t = row & (TDIM - 1);
    x[i] = tok[idx[row] * CDIM + c] + pos[t * CDIM + c];
}

// ---------------- standalone layernorm (only layer-0 ln1) ----------------
__global__ void ln_kernel(const float* __restrict__ x,
                          const float* __restrict__ g,
                          const float* __restrict__ b,
                          bf16* __restrict__ ohi, bf16* __restrict__ olo)
{
    int row = blockIdx.x;
    int c = threadIdx.x;
    float v = x[(size_t)row * CDIM + c];
    float s = v, s2 = v * v;
    #pragma unroll
    for (int o = 16; o; o >>= 1) {
        s  += __shfl_xor_sync(0xffffffffu, s,  o);
        s2 += __shfl_xor_sync(0xffffffffu, s2, o);
    }
    __shared__ float ss[8], ss2[8], m_sh, r_sh;
    int w = c >> 5, lane = c & 31;
    if (lane == 0) { ss[w] = s; ss2[w] = s2; }
    __syncthreads();
    if (c == 0) {
        float S = 0.f, S2 = 0.f;
        #pragma unroll
        for (int i = 0; i < 8; i++) { S += ss[i]; S2 += ss2[i]; }
        float m = S * (1.0f / CDIM);
        float var = S2 * (1.0f / CDIM) - m * m;
        m_sh = m; r_sh = rsqrtf(var + 1e-5f);
    }
    __syncthreads();
    float o = (v - m_sh) * r_sh * g[c] + b[c];
    size_t i = (size_t)row * CDIM + c;
    bf16 hi, lo; bf_split(o, hi, lo);
    ohi[i] = hi; olo[i] = lo;
}

// ---------------- weight transpose + split: W[K,N] -> T[N,K] hi/lo ----------------
__global__ void wsplit_kernel(const float* __restrict__ W,
                              bf16* __restrict__ Thi, bf16* __restrict__ Tlo,
                              int K, int N)
{
    __shared__ float t[32][33];
    int n0 = blockIdx.x << 5, k0 = blockIdx.y << 5;
    int tx = threadIdx.x, ty = threadIdx.y;  // (32,8)
    #pragma unroll
    for (int j = 0; j < 4; j++)
        t[ty + j * 8][tx] = W[(size_t)(k0 + ty + j * 8) * N + n0 + tx];
    __syncthreads();
    #pragma unroll
    for (int j = 0; j < 4; j++) {
        int nl = ty + j * 8;
        float v = t[tx][nl];
        size_t o = (size_t)(n0 + nl) * K + k0 + tx;
        bf16 hi, lo; bf_split(v, hi, lo);
        Thi[o] = hi; Tlo[o] = lo;
    }
}

// ---------------- HMMA split-bf16 GEMM (128x128 tile) ----------------
#define GST   10240
#define STAGE (4*GST)
#define GSMEM (2*STAGE)

__device__ __forceinline__ void g_fill(uint32_t st,
    const bf16* __restrict__ Ahi, const bf16* __restrict__ Alo,
    const bf16* __restrict__ Bhi, const bf16* __restrict__ Blo,
    int row0, int col0, int k0, int K, int tid)
{
    const bf16* base0 = Ahi + (size_t)row0 * K + k0;
    const bf16* base1 = Alo + (size_t)row0 * K + k0;
    const bf16* base2 = Bhi + (size_t)col0 * K + k0;
    const bf16* base3 = Blo + (size_t)col0 * K + k0;
    #pragma unroll
    for (int it = 0; it < 8; it++) {
        int i = tid + (it << 8);
        int mat = i >> 9, j = i & 511;
        int r = j >> 2, ch = j & 3;
        const bf16* src = (mat == 0) ? base0 : (mat == 1) ? base1 : (mat == 2) ? base2 : base3;
        cp16(st + mat * GST + r * 80 + ch * 16, src + (size_t)r * K + ch * 8);
    }
    CP_COMMIT();
}

template<bool GELU_, bool RES_, bool BF16OUT_, bool FP32OUT_>
__global__ void __launch_bounds__(256, 2) gemm_tc(
    const bf16* __restrict__ Ahi, const bf16* __restrict__ Alo,
    const bf16* __restrict__ Bhi, const bf16* __restrict__ Blo,
    const float* __restrict__ bias, const float* __restrict__ res,
    float* __restrict__ Cf, bf16* __restrict__ Chi, bf16* __restrict__ Clo,
    int M, int N, int K)
{
    extern __shared__ char smem[];
    const int tid  = threadIdx.x;
    const int wid  = tid >> 5;
    const int lane = tid & 31;
    const int warpM = wid & 3;
    const int warpN = wid >> 2;
    const int row0 = blockIdx.y << 7;
    const int col0 = blockIdx.x << 7;
    uint32_t sb = smem_u32(smem);

    float acc[2][8][4];
    #pragma unroll
    for (int mt = 0; mt < 2; mt++)
        #pragma unroll
        for (int nt = 0; nt < 8; nt++)
            #pragma unroll
            for (int j = 0; j < 4; j++) acc[mt][nt][j] = 0.f;

    const int nk = K >> 5;
    g_fill(sb, Ahi, Alo, Bhi, Blo, row0, col0, 0, K, tid);

    const uint32_t aoff_base = (uint32_t)((warpM * 32 + (lane & 15)) * 80 + ((lane >> 4) & 1) * 16);
    const uint32_t boff_base = (uint32_t)((warpN * 64 + ((lane >> 4) & 1) * 8 + (lane & 7)) * 80
                                          + ((lane >> 3) & 1) * 16);

    for (int kt = 0; kt < nk; kt++) {
        uint32_t st = sb + (uint32_t)(kt & 1) * STAGE;
        if (kt + 1 < nk) {
            g_fill(sb + (uint32_t)((kt + 1) & 1) * STAGE, Ahi, Alo, Bhi, Blo,
                   row0, col0, (kt + 1) << 5, K, tid);
            CP_WAIT(1);
        } else {
            CP_WAIT(0);
        }
        __syncthreads();

        #pragma unroll
        for (int k16 = 0; k16 < 2; k16++) {
            uint32_t ka = st + aoff_base + k16 * 32;
            uint32_t kb = st + boff_base + k16 * 32;
            uint32_t ah[2][4], al[2][4], bh[4][4], bl[4][4];
            ldmx4(ah[0], ka);
            ldmx4(ah[1], ka + 16 * 80);
            ldmx4(al[0], ka + GST);
            ldmx4(al[1], ka + GST + 16 * 80);
            #pragma unroll
            for (int nt2 = 0; nt2 < 4; nt2++) {
                ldmx4(bh[nt2], kb + 2 * GST + nt2 * (16 * 80));
                ldmx4(bl[nt2], kb + 3 * GST + nt2 * (16 * 80));
            }
            #pragma unroll
            for (int mt = 0; mt < 2; mt++)
                #pragma unroll
                for (int nt = 0; nt < 8; nt++) {
                    const uint32_t* bhp = &bh[nt >> 1][(nt & 1) * 2];
                    const uint32_t* blp = &bl[nt >> 1][(nt & 1) * 2];
                    mma16816(acc[mt][nt], ah[mt], bhp);
                    mma16816(acc[mt][nt], ah[mt], blp);
                    mma16816(acc[mt][nt], al[mt], bhp);
                }
        }
        __syncthreads();
    }

    const int g  = lane >> 2;
    const int tg = lane & 3;
    #pragma unroll
    for (int mt = 0; mt < 2; mt++) {
        #pragma unroll
        for (int half = 0; half < 2; half++) {
            int m = row0 + warpM * 32 + mt * 16 + g + half * 8;
            #pragma unroll
            for (int nt = 0; nt < 8; nt++) {
                int col = col0 + warpN * 64 + nt * 8 + tg * 2;
                float v0 = acc[mt][nt][half * 2 + 0];
                float v1 = acc[mt][nt][half * 2 + 1];
                if (bias) { v0 += bias[col]; v1 += bias[col + 1]; }
                if (GELU_) { v0 = gelu_f(v0); v1 = gelu_f(v1); }
                size_t o = (size_t)m * N + col;
                if (RES_) {
                    float2 r2 = *reinterpret_cast<const float2*>(&res[o]);
                    v0 += r2.x; v1 += r2.y;
                }
                if (FP32OUT_) {
                    *reinterpret_cast<float2*>(&Cf[o]) = make_float2(v0, v1);
                }
                if (BF16OUT_) {
                    uint32_t hh, ll;
                    pack2(v0, v1, hh, ll);
                    *reinterpret_cast<uint32_t*>(&Chi[o]) = hh;
                    *reinterpret_cast<uint32_t*>(&Clo[o]) = ll;
                }
            }
        }
    }
}

// ---------------- fused GEMM + residual + LayerNorm (128x256 tile, 512 thr) ----
#define FST_A 10240
#define FST_B 20480
#define FSTAGE (2*FST_A + 2*FST_B)   // 61440
#define FRED  (2*FSTAGE)
#define FSMEM (2*FSTAGE + 1024)

__device__ __forceinline__ void f_fill(uint32_t st,
    const bf16* __restrict__ Ahi, const bf16* __restrict__ Alo,
    const bf16* __restrict__ Bhi, const bf16* __restrict__ Blo,
    int row0, int k0, int K, int tid)
{
    const bf16* a0 = Ahi + (size_t)row0 * K + k0;
    const bf16* a1 = Alo + (size_t)row0 * K + k0;
    const bf16* b0 = Bhi + k0;
    const bf16* b1 = Blo + k0;
    #pragma unroll
    for (int it = 0; it < 6; it++) {
        int i = tid + it * 512;
        if (i < 1024) {
            int mat = i >> 9, j = i & 511, r = j >> 2, ch = j & 3;
            const bf16* src = mat ? a1 : a0;
            cp16(st + mat * FST_A + r * 80 + ch * 16, src + (size_t)r * K + ch * 8);
        } else {
            int i2 = i - 1024;
            int mat = i2 >> 10, j = i2 & 1023, r = j >> 2, ch = j & 3;
            const bf16* src = mat ? b1 : b0;
            cp16(st + 2 * FST_A + mat * FST_B + r * 80 + ch * 16, src + (size_t)r * K + ch * 8);
        }
    }
    CP_COMMIT();
}

__global__ void __launch_bounds__(512, 1) gemm_fused_ln(
    const bf16* __restrict__ Ahi, const bf16* __restrict__ Alo,
    const bf16* __restrict__ Bhi, const bf16* __restrict__ Blo,
    const float* __restrict__ bias,
    float* __restrict__ x,
    const float* __restrict__ lng, const float* __restrict__ lnb,
    bf16* __restrict__ Chi, bf16* __restrict__ Clo,
    int K)
{
    extern __shared__ char smem[];
    const int tid  = threadIdx.x;
    const int wid  = tid >> 5;
    const int lane = tid & 31;
    const int warpM = wid & 3;
    const int warpN = wid >> 2;
    const int row0 = blockIdx.y << 7;
    uint32_t sb = smem_u32(smem);
    float* rsum = (float*)(smem + FRED);
    float* rsq  = (float*)(smem + FRED + 512);

    if (tid < 128) { rsum[tid] = 0.f; rsq[tid] = 0.f; }

    float acc[2][8][4];
    #pragma unroll
    for (int mt = 0; mt < 2; mt++)
        #pragma unroll
        for (int nt = 0; nt < 8; nt++)
            #pragma unroll
            for (int j = 0; j < 4; j++) acc[mt][nt][j] = 0.f;

    const int nk = K >> 5;
    f_fill(sb, Ahi, Alo, Bhi, Blo, row0, 0, K, tid);

    const uint32_t aoff = (uint32_t)((warpM * 32 + (lane & 15)) * 80 + ((lane >> 4) & 1) * 16);
    const uint32_t boff = (uint32_t)(2 * FST_A
                         + (warpN * 64 + ((lane >> 4) & 1) * 8 + (lane & 7)) * 80
                         + ((lane >> 3) & 1) * 16);

    for (int kt = 0; kt < nk; kt++) {
        uint32_t st = sb + (uint32_t)(kt & 1) * FSTAGE;
        if (kt + 1 < nk) {
            f_fill(sb + (uint32_t)((kt + 1) & 1) * FSTAGE, Ahi, Alo, Bhi, Blo,
                   row0, (kt + 1) << 5, K, tid);
            CP_WAIT(1);
        } else {
            CP_WAIT(0);
        }
        __syncthreads();

        #pragma unroll
        for (int k16 = 0; k16 < 2; k16++) {
            uint32_t ka = st + aoff + k16 * 32;
            uint32_t kb = st + boff + k16 * 32;
            uint32_t ah[2][4], al[2][4], bh[4][4], bl[4][4];
            ldmx4(ah[0], ka);
            ldmx4(ah[1], ka + 16 * 80);
            ldmx4(al[0], ka + FST_A);
            ldmx4(al[1], ka + FST_A + 16 * 80);
            #pragma unroll
            for (int nt2 = 0; nt2 < 4; nt2++) {
                ldmx4(bh[nt2], kb + nt2 * (16 * 80));
                ldmx4(bl[nt2], kb + FST_B + nt2 * (16 * 80));
            }
            #pragma unroll
            for (int mt = 0; mt < 2; mt++)
                #pragma unroll
                for (int nt = 0; nt < 8; nt++) {
                    const uint32_t* bhp = &bh[nt >> 1][(nt & 1) * 2];
                    const uint32_t* blp = &bl[nt >> 1][(nt & 1) * 2];
                    mma16816(acc[mt][nt], ah[mt], bhp);
                    mma16816(acc[mt][nt], ah[mt], blp);
                    mma16816(acc[mt][nt], al[mt], bhp);
                }
        }
        __syncthreads();
    }

    const int g  = lane >> 2;
    const int tg = lane & 3;
    #pragma unroll
    for (int mt = 0; mt < 2; mt++) {
        #pragma unroll
        for (int half = 0; half < 2; half++) {
            int ml = warpM * 32 + mt * 16 + g + half * 8;
            int m = row0 + ml;
            float s = 0.f, s2 = 0.f;
            #pragma unroll
            for (int nt = 0; nt < 8; nt++) {
                int col = warpN * 64 + nt * 8 + tg * 2;
                float v0 = acc[mt][nt][half * 2 + 0] + bias[col];
                float v1 = acc[mt][nt][half * 2 + 1] + bias[col + 1];
                float2 r2 = *reinterpret_cast<const float2*>(&x[(size_t)m * CDIM + col]);
                v0 += r2.x; v1 += r2.y;
                acc[mt][nt][half * 2 + 0] = v0;
                acc[mt][nt][half * 2 + 1] = v1;
                s += v0 + v1;
                s2 += v0 * v0 + v1 * v1;
            }
            s  += __shfl_xor_sync(0xffffffffu, s, 1);
            s  += __shfl_xor_sync(0xffffffffu, s, 2);
            s2 += __shfl_xor_sync(0xffffffffu, s2, 1);
            s2 += __shfl_xor_sync(0xffffffffu, s2, 2);
            if (tg == 0) {
                atomicAdd(&rsum[ml], s);
                atomicAdd(&rsq[ml], s2);
            }
        }
    }
    __syncthreads();
    if (tid < 128) {
        float m = rsum[tid] * (1.0f / CDIM);
        float var = rsq[tid] * (1.0f / CDIM) - m * m;
        rsum[tid] = m;
        rsq[tid]  = rsqrtf(var + 1e-5f);
    }
    __syncthreads();
    #pragma unroll
    for (int mt = 0; mt < 2; mt++) {
        #pragma unroll
        for (int half = 0; half < 2; half++) {
            int ml = warpM * 32 + mt * 16 + g + half * 8;
            int m = row0 + ml;
            float mu = rsum[ml], rst = rsq[ml];
            #pragma unroll
            for (int nt = 0; nt < 8; nt++) {
                int col = warpN * 64 + nt * 8 + tg * 2;
                float v0 = acc[mt][nt][half * 2 + 0];
                float v1 = acc[mt][nt][half * 2 + 1];
                size_t o = (size_t)m * CDIM + col;
                *reinterpret_cast<float2*>(&x[o]) = make_float2(v0, v1);
                float h0 = (v0 - mu) * rst * lng[col] + lnb[col];
                float h1 = (v1 - mu) * rst * lng[col + 1] + lnb[col + 1];
                uint32_t hh, ll;
                pack2(h0, h1, hh, ll);
                *reinterpret_cast<uint32_t*>(&Chi[o]) = hh;
                *reinterpret_cast<uint32_t*>(&Clo[o]) = ll;
            }
        }
    }
}

// ================= HMMA flash attention, q-tile 128, warp-private rows =========
// smem: Qhi[128x32]@0 (10240), Qlo@10240, stages@20480 (2 x 20480: Khi|Klo|Vhi|Vlo)
#define AQ_LO  10240
#define ASTG   20480
#define ASTGSZ 20480
#define ASMEM  61440
#define ASCALE 0.17677669529663687f

__device__ __forceinline__ void a_fill_kv(uint32_t dst, const bf16* __restrict__ qh,
                                          const bf16* __restrict__ ql,
                                          size_t tokbase, int hcol, int k0, int tid)
{
    int r = tid >> 2, ch = tid & 3;
    size_t rowoff = tokbase + (size_t)(k0 + r) * 768;
    uint32_t so = (uint32_t)(r * 80 + ch * 16);
    cp16(dst + so,         qh + rowoff + 256 + hcol + ch * 8);
    cp16(dst + 5120 + so,  ql + rowoff + 256 + hcol + ch * 8);
    cp16(dst + 10240 + so, qh + rowoff + 512 + hcol + ch * 8);
    cp16(dst + 15360 + so, ql + rowoff + 512 + hcol + ch * 8);
}

__global__ void __launch_bounds__(256, 1) attn_tc(
    const bf16* __restrict__ qh, const bf16* __restrict__ ql,
    bf16* __restrict__ yhi, bf16* __restrict__ ylo)
{
    extern __shared__ char smem[];
    uint32_t sb = smem_u32(smem);
    const int tid = threadIdx.x, wid = tid >> 5, lane = tid & 31;
    const int g = lane >> 2, tg = lane & 3;
    const int qt = (int)gridDim.x - 1 - (int)blockIdx.x;   // heavy tiles first
    const int bh = blockIdx.y;
    const int b = bh >> 3, h = bh & 7;
    const int q0 = qt * 128, hcol = h * 32;
    const size_t tokbase = (size_t)b * TDIM * 768;

    // Q fill: 128 rows x 32 cols, hi+lo (1024 cp16)
    #pragma unroll
    for (int it = 0; it < 4; it++) {
        int i = tid + (it << 8);
        int mat = i >> 9, j = i & 511, r = j >> 2, ch = j & 3;
        const bf16* src = mat ? ql : qh;
        cp16(sb + (uint32_t)mat * 10240 + r * 80 + ch * 16,
             src + tokbase + (size_t)(q0 + r) * 768 + hcol + ch * 8);
    }
    a_fill_kv(sb + ASTG, qh, ql, tokbase, hcol, 0, tid);
    CP_COMMIT();

    const int r0 = wid * 16 + g;           // local q rows r0, r0+8
    float m0 = -1e30f, m1 = -1e30f, l0 = 0.f, l1 = 0.f;
    float oc[4][4];
    #pragma unroll
    for (int n = 0; n < 4; n++)
        #pragma unroll
        for (int j = 0; j < 4; j++) oc[n][j] = 0.f;

    const uint32_t qa = sb + (uint32_t)((wid * 16 + (lane & 15)) * 80 + ((lane >> 4) & 1) * 16);
    const uint32_t kboff = (uint32_t)((((lane >> 4) & 1) * 8 + (lane & 7)) * 80
                                      + ((lane >> 3) & 1) * 16);
    const uint32_t vaoff = (uint32_t)((lane & 15) * 80 + ((lane >> 4) & 1) * 16);

    const int nkt = 2 * qt + 2;
    for (int kt = 0; kt < nkt; kt++) {
        CP_WAIT(0);
        __syncthreads();
        uint32_t stg = sb + ASTG + (uint32_t)(kt & 1) * ASTGSZ;

        // ---- S = Q K^T : warp-private 16 rows x full 64 keys ----
        float sc[8][4];
        #pragma unroll
        for (int n = 0; n < 8; n++)
            #pragma unroll
            for (int j = 0; j < 4; j++) sc[n][j] = 0.f;

        #pragma unroll
        for (int k16 = 0; k16 < 2; k16++) {
            uint32_t ah[4], al[4], bhh[4][4], bll[4][4];
            ldmx4(ah, qa + k16 * 32);
            ldmx4(al, qa + AQ_LO + k16 * 32);
            #pragma unroll
            for (int nt2 = 0; nt2 < 4; nt2++) {
                ldmx4(bhh[nt2], stg + kboff + k16 * 32 + nt2 * (16 * 80));
                ldmx4(bll[nt2], stg + 5120 + kboff + k16 * 32 + nt2 * (16 * 80));
            }
            #pragma unroll
            for (int n = 0; n < 8; n++) {
                const uint32_t* bp = &bhh[n >> 1][(n & 1) * 2];
                const uint32_t* lp = &bll[n >> 1][(n & 1) * 2];
                mma16816(sc[n], ah, bp);
                mma16816(sc[n], ah, lp);
                mma16816(sc[n], al, bp);
            }
        }

        // ---- scale + causal mask (per-warp skip when fully unmasked) ----
        const int k0g = kt * 64;
        const bool needmask = (k0g + 63 > q0 + wid * 16);
        #pragma unroll
        for (int n = 0; n < 8; n++)
            #pragma unroll
            for (int j = 0; j < 4; j++) {
                float s = sc[n][j] * ASCALE;
                if (needmask) {
                    int kc = k0g + n * 8 + tg * 2 + (j & 1);
                    int qr = q0 + r0 + ((j < 2) ? 0 : 8);
                    if (kc > qr) s = -1e30f;
                }
                sc[n][j] = s;
            }

        // prefetch next KV (overlaps softmax + PV)
        if (kt + 1 < nkt) {
            a_fill_kv(sb + ASTG + (uint32_t)((kt + 1) & 1) * ASTGSZ,
                      qh, ql, tokbase, hcol, (kt + 1) * 64, tid);
            CP_COMMIT();
        }

        // ---- fully in-warp row stats (4-lane groups) ----
        float mx0 = -1e30f, mx1 = -1e30f;
        #pragma unroll
        for (int n = 0; n < 8; n++) {
            mx0 = fmaxf(mx0, fmaxf(sc[n][0], sc[n][1]));
            mx1 = fmaxf(mx1, fmaxf(sc[n][2], sc[n][3]));
        }
        mx0 = fmaxf(mx0, __shfl_xor_sync(0xffffffffu, mx0, 1));
        mx0 = fmaxf(mx0, __shfl_xor_sync(0xffffffffu, mx0, 2));
        mx1 = fmaxf(mx1, __shfl_xor_sync(0xffffffffu, mx1, 1));
        mx1 = fmaxf(mx1, __shfl_xor_sync(0xffffffffu, mx1, 2));
        float n0 = fmaxf(m0, mx0), n1 = fmaxf(m1, mx1);
        float al0 = __expf(m0 - n0), al1 = __expf(m1 - n1);

        float s0 = 0.f, s1 = 0.f;
        #pragma unroll
        for (int n = 0; n < 8; n++) {
            #pragma unroll
            for (int j = 0; j < 4; j++) {
                float p = __expf(sc[n][j] - ((j < 2) ? n0 : n1));
                sc[n][j] = p;
                if (j < 2) s0 += p; else s1 += p;
            }
        }
        s0 += __shfl_xor_sync(0xffffffffu, s0, 1);
        s0 += __shfl_xor_sync(0xffffffffu, s0, 2);
        s1 += __shfl_xor_sync(0xffffffffu, s1, 1);
        s1 += __shfl_xor_sync(0xffffffffu, s1, 2);
        l0 = l0 * al0 + s0; l1 = l1 * al1 + s1;
        m0 = n0; m1 = n1;

        // ---- P fragments (C-frag -> A-frag identity, fast pack) ----
        uint32_t ph[4][4], pl[4][4];
        #pragma unroll
        for (int c = 0; c < 4; c++) {
            pack2(sc[2*c][0],   sc[2*c][1],   ph[c][0], pl[c][0]);
            pack2(sc[2*c][2],   sc[2*c][3],   ph[c][1], pl[c][1]);
            pack2(sc[2*c+1][0], sc[2*c+1][1], ph[c][2], pl[c][2]);
            pack2(sc[2*c+1][2], sc[2*c+1][3], ph[c][3], pl[c][3]);
        }
        #pragma unroll
        for (int n = 0; n < 4; n++) {
            oc[n][0] *= al0; oc[n][1] *= al0;
            oc[n][2] *= al1; oc[n][3] *= al1;
        }

        // ---- O += P V (V via ldmatrix.trans, 4 k16-chunks) ----
        #pragma unroll
        for (int c = 0; c < 4; c++) {
            uint32_t va = stg + 10240 + vaoff + (uint32_t)c * (16 * 80);
            uint32_t vh0[4], vh1[4], vl0[4], vl1[4];
            ldmx4t(vh0, va);
            ldmx4t(vh1, va + 32);
            ldmx4t(vl0, va + 5120);
            ldmx4t(vl1, va + 5120 + 32);
            #pragma unroll
            for (int n = 0; n < 4; n++) {
                const uint32_t* bp = (n < 2) ? &vh0[(n & 1) * 2] : &vh1[(n & 1) * 2];
                const uint32_t* lp = (n < 2) ? &vl0[(n & 1) * 2] : &vl1[(n & 1) * 2];
                mma16816(oc[n], ph[c], bp);
                mma16816(oc[n], pl[c], bp);
                mma16816(oc[n], ph[c], lp);
            }
        }
    }

    // ---- store straight from registers (warp-private rows) ----
    float il0 = 1.0f / l0, il1 = 1.0f / l1;
    size_t grow0 = (size_t)(b * TDIM + q0 + r0) * CDIM + hcol;
    size_t grow1 = grow0 + 8 * CDIM;
    #pragma unroll
    for (int n = 0; n < 4; n++) {
        int co = n * 8 + tg * 2;
        uint32_t hh, ll;
        pack2(oc[n][0] * il0, oc[n][1] * il0, hh, ll);
        *reinterpret_cast<uint32_t*>(&yhi[grow0 + co]) = hh;
        *reinterpret_cast<uint32_t*>(&ylo[grow0 + co]) = ll;
        pack2(oc[n][2] * il1, oc[n][3] * il1, hh, ll);
        *reinterpret_cast<uint32_t*>(&yhi[grow1 + co]) = hh;
        *reinterpret_cast<uint32_t*>(&ylo[grow1 + co]) = ll;
    }
}

// ---------------- host orchestration ----------------
extern "C" void kernel_launch(void* const* d_in, const int* in_sizes, int n_in,
                              void* d_out, int out_size)
{
    const int*   idx     = (const int*)  d_in[0];
    const float* tok_emb = (const float*)d_in[1];
    const float* pos_emb = (const float*)d_in[2];
    const float* ln1_g   = (const float*)d_in[3];
    const float* ln1_b   = (const float*)d_in[4];
    const float* wqkv    = (const float*)d_in[5];
    const float* bqkv    = (const float*)d_in[6];
    const float* wo      = (const float*)d_in[7];
    const float* bo      = (const float*)d_in[8];
    const float* ln2_g   = (const float*)d_in[9];
    const float* ln2_b   = (const float*)d_in[10];
    const float* wfc     = (const float*)d_in[11];
    const float* bfc     = (const float*)d_in[12];
    const float* wpr     = (const float*)d_in[13];
    const float* bpr     = (const float*)d_in[14];
    const float* lnf_g   = (const float*)d_in[15];
    const float* lnf_b   = (const float*)d_in[16];
    const float* w_lm    = (const float*)d_in[17];
    float* out = (float*)d_out;

    float *xp;
    bf16 *hhi, *hlo, *qvh, *qvl, *yhi, *ylo, *fhi, *flo;
    bf16 *wqh, *wql, *woh, *wol, *wfh, *wfl, *wph, *wpl, *wlh, *wll;
    cudaGetSymbolAddress((void**)&xp,   g_x);
    cudaGetSymbolAddress((void**)&hhi,  g_hhi);  cudaGetSymbolAddress((void**)&hlo, g_hlo);
    cudaGetSymbolAddress((void**)&qvh,  g_qvh);  cudaGetSymbolAddress((void**)&qvl, g_qvl);
    cudaGetSymbolAddress((void**)&yhi,  g_yhi);  cudaGetSymbolAddress((void**)&ylo, g_ylo);
    cudaGetSymbolAddress((void**)&fhi,  g_fhi);  cudaGetSymbolAddress((void**)&flo, g_flo);
    cudaGetSymbolAddress((void**)&wqh,  g_wqh);  cudaGetSymbolAddress((void**)&wql, g_wql);
    cudaGetSymbolAddress((void**)&woh,  g_woh);  cudaGetSymbolAddress((void**)&wol, g_wol);
    cudaGetSymbolAddress((void**)&wfh,  g_wfh);  cudaGetSymbolAddress((void**)&wfl, g_wfl);
    cudaGetSymbolAddress((void**)&wph,  g_wph);  cudaGetSymbolAddress((void**)&wpl, g_wpl);
    cudaGetSymbolAddress((void**)&wlh,  g_wlh);  cudaGetSymbolAddress((void**)&wll, g_wll);

    cudaFuncSetAttribute(gemm_tc<false, false, false, true>,
                         cudaFuncAttributeMaxDynamicSharedMemorySize, GSMEM);
    cudaFuncSetAttribute(gemm_tc<true, false, true, false>,
                         cudaFuncAttributeMaxDynamicSharedMemorySize, GSMEM);
    cudaFuncSetAttribute(gemm_tc<false, false, true, false>,
                         cudaFuncAttributeMaxDynamicSharedMemorySize, GSMEM);
    cudaFuncSetAttribute(gemm_fused_ln,
                         cudaFuncAttributeMaxDynamicSharedMemorySize, FSMEM);
    cudaFuncSetAttribute(attn_tc,
                         cudaFuncAttributeMaxDynamicSharedMemorySize, ASMEM);

    // ---- weight prep (transpose + bf16 split) ----
    dim3 wb(32, 8);
    for (int l = 0; l < LAYERS; l++) {
        wsplit_kernel<<<dim3(24, 8), wb>>>(wqkv + (size_t)l * CDIM * 3 * CDIM,
                                           wqh + (size_t)l * 3 * CDIM * CDIM,
                                           wql + (size_t)l * 3 * CDIM * CDIM, CDIM, 3 * CDIM);
        wsplit_kernel<<<dim3(8, 8),  wb>>>(wo + (size_t)l * CDIM * CDIM,
                                           woh + (size_t)l * CDIM * CDIM,
                                           wol + (size_t)l * CDIM * CDIM, CDIM, CDIM);
        wsplit_kernel<<<dim3(32, 8), wb>>>(wfc + (size_t)l * CDIM * FFDIM,
                                           wfh + (size_t)l * FFDIM * CDIM,
                                           wfl + (size_t)l * FFDIM * CDIM, CDIM, FFDIM);
        wsplit_kernel<<<dim3(8, 32), wb>>>(wpr + (size_t)l * FFDIM * CDIM,
                                           wph + (size_t)l * CDIM * FFDIM,
                                           wpl + (size_t)l * CDIM * FFDIM, FFDIM, CDIM);
    }
    wsplit_kernel<<<dim3(4, 8), wb>>>(w_lm, wlh, wll, CDIM, VDIM);

    embed_kernel<<<(NTOK * CDIM + 255) / 256, 256>>>(idx, tok_emb, pos_emb, xp);
    ln_kernel<<<NTOK, 256>>>(xp, ln1_g, ln1_b, hhi, hlo);

    for (int l = 0; l < LAYERS; l++) {
        const float* bq  = bqkv + (size_t)l * 3 * CDIM;
        const float* bo_ = bo   + (size_t)l * CDIM;
        const float* bf  = bfc  + (size_t)l * FFDIM;
        const float* bp  = bpr  + (size_t)l * CDIM;
        bf16* Wqh = wqh + (size_t)l * 3 * CDIM * CDIM;  bf16* Wql = wql + (size_t)l * 3 * CDIM * CDIM;
        bf16* Woh = woh + (size_t)l * CDIM * CDIM;      bf16* Wol = wol + (size_t)l * CDIM * CDIM;
        bf16* Wfh = wfh + (size_t)l * FFDIM * CDIM;     bf16* Wfl = wfl + (size_t)l * FFDIM * CDIM;
        bf16* Wph = wph + (size_t)l * CDIM * FFDIM;     bf16* Wpl = wpl + (size_t)l * CDIM * FFDIM;

        gemm_tc<false, false, true, false><<<dim3(6, NTOK / 128), 256, GSMEM>>>(
            hhi, hlo, Wqh, Wql, bq, nullptr, nullptr, qvh, qvl, NTOK, 3 * CDIM, CDIM);

        attn_tc<<<dim3(TDIM / 128, BDIM * HEADS), 256, ASMEM>>>(qvh, qvl, yhi, ylo);

        gemm_fused_ln<<<dim3(1, NTOK / 128), 512, FSMEM>>>(
            yhi, ylo, Woh, Wol, bo_, xp,
            ln2_g + (size_t)l * CDIM, ln2_b + (size_t)l * CDIM, hhi, hlo, CDIM);

        gemm_tc<true, false, true, false><<<dim3(8, NTOK / 128), 256, GSMEM>>>(
            hhi, hlo, Wfh, Wfl, bf, nullptr, nullptr, fhi, flo, NTOK, FFDIM, CDIM);

        const float* ng = (l + 1 < LAYERS) ? ln1_g + (size_t)(l + 1) * CDIM : lnf_g;
        const float* nb = (l + 1 < LAYERS) ? ln1_b + (size_t)(l + 1) * CDIM : lnf_b;
        gemm_fused_ln<<<dim3(1, NTOK / 128), 512, FSMEM>>>(
            fhi, flo, Wph, Wpl, bp, xp, ng, nb, hhi, hlo, FFDIM);
    }

    gemm_tc<false, false, false, true><<<dim3(1, NTOK / 128), 256, GSMEM>>>(
        hhi, hlo, wlh, wll, nullptr, nullptr, out, nullptr, nullptr, NTOK, VDIM, CDIM);
}